// round 2
// baseline (speedup 1.0000x reference)
#include <cuda_runtime.h>
#include <math.h>
#include <stdint.h>

// Problem constants (fixed shapes from reference setup_inputs)
#define NROWS 262144
#define DX 64
#define DZ 32
#define NB 1024
#define TR 128                       // rows per block in main kernel
#define NCHUNK (NB / 128)            // 8 bin-chunks of 128
#define GRID_MAIN (NROWS / TR)       // 2048
#define GRID_SEG 148
#define SEG_CH ((NROWS + GRID_SEG - 1) / GRID_SEG)  // 1772

// Scratch (static device globals; no runtime allocation)
__device__ float  g_z[NROWS * DZ];            // 32 MB
__device__ int    g_idx[NROWS];               // 1 MB
__device__ float  g_hn[NB];                   // 0.5*||v_b||^2
__device__ float  g_partc[GRID_SEG * NB];     // per-CTA count partials
__device__ float  g_parts[GRID_SEG * NB * DZ];// per-CTA sum_z partials (~19 MB)
__device__ double g_recon;
__device__ double g_commit;

// ---------------------------------------------------------------------------
// init: half-norms of codebook + zero loss accumulators
// ---------------------------------------------------------------------------
__global__ void k_init(const float* __restrict__ vectors) {
    int b = blockIdx.x * blockDim.x + threadIdx.x;
    if (b < NB) {
        float s = 0.f;
#pragma unroll
        for (int d = 0; d < DZ; ++d) {
            float v = vectors[b * DZ + d];
            s = fmaf(v, v, s);
        }
        g_hn[b] = 0.5f * s;
    }
    if (b == 0) { g_recon = 0.0; g_commit = 0.0; }
}

// ---------------------------------------------------------------------------
// main fused kernel: encoder -> scores/argmin -> gather -> decoder -> losses
// One block handles TR=128 rows. 256 threads.
// ---------------------------------------------------------------------------
// shared layout (floats):
//   s_x   [128][64]    8192
//   s_we  [64][32]     2048
//   s_wd  [32][64]     2048
//   s_z   [128][33]    4224  (padded vs 32 to kill bank conflicts)
//   s_v   [128][33]    4224  (padded)
//   s_hn  [128]         128
//   s_q   [128][32]    4096
//   s_benc[32], s_bdec[64], s_ridx[128](int), s_red[16]
#define SM_X    0
#define SM_WE   (SM_X + 8192)
#define SM_WD   (SM_WE + 2048)
#define SM_Z    (SM_WD + 2048)
#define SM_V    (SM_Z + 4224)
#define SM_HN   (SM_V + 4224)
#define SM_Q    (SM_HN + 128)
#define SM_BENC (SM_Q + 4096)
#define SM_BDEC (SM_BENC + 32)
#define SM_RIDX (SM_BDEC + 64)
#define SM_RED  (SM_RIDX + 128)
#define SM_MAIN_FLOATS (SM_RED + 16)
#define SMEM_MAIN (SM_MAIN_FLOATS * 4)

__global__ void __launch_bounds__(256, 2) k_main(
    const float* __restrict__ x, const float* __restrict__ W_enc,
    const float* __restrict__ b_enc, const float* __restrict__ vectors,
    const float* __restrict__ W_dec, const float* __restrict__ b_dec)
{
    extern __shared__ float sm[];
    float* s_x    = sm + SM_X;
    float* s_we   = sm + SM_WE;
    float* s_wd   = sm + SM_WD;
    float* s_z    = sm + SM_Z;
    float* s_v    = sm + SM_V;
    float* s_hn   = sm + SM_HN;
    float* s_q    = sm + SM_Q;
    float* s_benc = sm + SM_BENC;
    float* s_bdec = sm + SM_BDEC;
    int*   s_ridx = (int*)(sm + SM_RIDX);
    float* s_red  = sm + SM_RED;

    const int tid  = threadIdx.x;
    const int row0 = blockIdx.x * TR;
    const unsigned FULL = 0xFFFFFFFFu;

    // ---- load x tile + weights ----
    {
        const float4* xs = (const float4*)(x + (size_t)row0 * DX);
        float4* sx4 = (float4*)s_x;
        for (int n = tid; n < TR * DX / 4; n += 256) sx4[n] = xs[n];
        for (int n = tid; n < DX * DZ; n += 256) s_we[n] = W_enc[n];
        for (int n = tid; n < DZ * DX; n += 256) s_wd[n] = W_dec[n];
        if (tid < DZ) s_benc[tid] = b_enc[tid];
        if (tid < DX) s_bdec[tid] = b_dec[tid];
    }
    __syncthreads();

    // ---- stage 1: z = x @ W_enc + b_enc ----
    {
        int col = tid & 31;
        int rb  = (tid >> 5) * 16;
        for (int rr = 0; rr < 16; ++rr) {
            int r = rb + rr;
            float acc = s_benc[col];
#pragma unroll 16
            for (int k = 0; k < DX; ++k)
                acc = fmaf(s_x[r * DX + k], s_we[k * DZ + col], acc);
            s_z[r * 33 + col] = acc;
            g_z[(size_t)(row0 + r) * DZ + col] = acc;
        }
    }
    __syncthreads();

    // ---- stage 2: scores + running argmax (argmin of d2) ----
    const int rg = tid >> 4, cg = tid & 15;
    const int rbase = rg * 8, cbase = cg * 8;
    float best[8]; int bidx[8];
#pragma unroll
    for (int i = 0; i < 8; i++) { best[i] = -3.4e38f; bidx[i] = 0; }

    for (int ch = 0; ch < NCHUNK; ++ch) {
        // load codebook chunk (padded)
        for (int n = tid; n < 128 * DZ; n += 256) {
            int c = n >> 5, d = n & 31;
            s_v[c * 33 + d] = vectors[(size_t)(ch * 128 + c) * DZ + d];
        }
        if (tid < 128) s_hn[tid] = g_hn[ch * 128 + tid];
        __syncthreads();

        float acc[8][8];
#pragma unroll
        for (int i = 0; i < 8; i++)
#pragma unroll
            for (int j = 0; j < 8; j++) acc[i][j] = 0.f;

#pragma unroll 8
        for (int kk = 0; kk < DZ; ++kk) {
            float a[8], b[8];
#pragma unroll
            for (int i = 0; i < 8; i++) a[i] = s_z[(rbase + i) * 33 + kk];
#pragma unroll
            for (int j = 0; j < 8; j++) b[j] = s_v[(cbase + j) * 33 + kk];
#pragma unroll
            for (int i = 0; i < 8; i++)
#pragma unroll
                for (int j = 0; j < 8; j++)
                    acc[i][j] = fmaf(a[i], b[j], acc[i][j]);
        }
        // score = z.v - 0.5||v||^2 ; ascending bin order => strict '>' keeps
        // the first (lowest-index) max = jnp.argmin(d2) tie behavior
#pragma unroll
        for (int j = 0; j < 8; j++) {
            float hn = s_hn[cbase + j];
            int bin = ch * 128 + cbase + j;
#pragma unroll
            for (int i = 0; i < 8; i++) {
                float sc = acc[i][j] - hn;
                if (sc > best[i]) { best[i] = sc; bidx[i] = bin; }
            }
        }
        __syncthreads();  // protect s_v before next chunk overwrites
    }

    // ---- reduce best across the 16 threads (same rows, lanes form 16-groups)
#pragma unroll
    for (int i = 0; i < 8; i++) {
        float bs = best[i]; int bi = bidx[i];
#pragma unroll
        for (int off = 8; off >= 1; off >>= 1) {
            float os = __shfl_xor_sync(FULL, bs, off);
            int   oi = __shfl_xor_sync(FULL, bi, off);
            if (os > bs || (os == bs && oi < bi)) { bs = os; bi = oi; }
        }
        if (cg == 0) {
            s_ridx[rbase + i] = bi;
            g_idx[row0 + rbase + i] = bi;
        }
    }
    __syncthreads();

    // ---- gather quantized + commitment partial ----
    float commit = 0.f;
    for (int n = tid; n < TR * DZ; n += 256) {
        int r = n >> 5, d = n & 31;
        float q = vectors[(size_t)s_ridx[r] * DZ + d];
        s_q[r * DZ + d] = q;
        float zz = s_z[r * 33 + d];
        float df = q - zz;
        commit = fmaf(df, df, commit);
    }
    __syncthreads();  // s_q ready

    // ---- decoder mu = q @ W_dec + b_dec, reconstruction partial ----
    float recon = 0.f;
    {
        int c  = tid & 63;
        int rb = (tid >> 6) * 32;
        float wcol[DZ];
#pragma unroll
        for (int k = 0; k < DZ; k++) wcol[k] = s_wd[k * DX + c];
        float bd = s_bdec[c];
        for (int rr = 0; rr < 32; ++rr) {
            int r = rb + rr;
            float m = bd;
#pragma unroll
            for (int k = 0; k < DZ; k++)
                m = fmaf(s_q[r * DZ + k], wcol[k], m);
            float d = s_x[r * DX + c] - m;
            recon = fmaf(d, d, recon);
        }
    }

    // ---- block reduce losses -> double atomics ----
#pragma unroll
    for (int off = 16; off; off >>= 1) {
        commit += __shfl_xor_sync(FULL, commit, off);
        recon  += __shfl_xor_sync(FULL, recon, off);
    }
    int wid = tid >> 5, lid = tid & 31;
    if (lid == 0) { s_red[wid] = commit; s_red[8 + wid] = recon; }
    __syncthreads();
    if (tid == 0) {
        float cs = 0.f, rs = 0.f;
        for (int w = 0; w < 8; w++) { cs += s_red[w]; rs += s_red[8 + w]; }
        atomicAdd(&g_commit, (double)cs);
        atomicAdd(&g_recon,  (double)rs);
    }
}

// ---------------------------------------------------------------------------
// segment sum: per-SM shared-memory histogram of counts and sum_z
// ---------------------------------------------------------------------------
#define SMEM_SEG ((NB * DZ + NB) * 4)

__global__ void __launch_bounds__(256, 1) k_segsum() {
    extern __shared__ float sm[];
    float* s_sum = sm;            // [1024][32]
    float* s_cnt = sm + NB * DZ;  // [1024]
    int tid = threadIdx.x;
    for (int n = tid; n < NB * DZ + NB; n += 256) sm[n] = 0.f;
    __syncthreads();

    int start = blockIdx.x * SEG_CH;
    int end = min(NROWS, start + SEG_CH);
    int d = tid & 31, rs = tid >> 5;
    for (int r = start + rs; r < end; r += 8) {
        int b = g_idx[r];
        atomicAdd(&s_sum[b * DZ + d], g_z[(size_t)r * DZ + d]);
        if (d == 0) atomicAdd(&s_cnt[b], 1.f);
    }
    __syncthreads();
    for (int n = tid; n < NB * DZ; n += 256)
        g_parts[(size_t)blockIdx.x * NB * DZ + n] = s_sum[n];
    for (int n = tid; n < NB; n += 256)
        g_partc[blockIdx.x * NB + n] = s_cnt[n];
}

// ---------------------------------------------------------------------------
// finalize: reduce partials, EMA, dead-code scan (exact), write outputs
// out layout: [0]=loss, [1..32768]=new_vectors, [32769..33792]=assign_ema
// ---------------------------------------------------------------------------
__global__ void k_finalize(const float* __restrict__ vectors,
                           const float* __restrict__ assignments,
                           const float* __restrict__ noise,
                           float* __restrict__ out)
{
    __shared__ float s_cnt[NB];
    __shared__ float s_aem[NB];
    __shared__ unsigned char s_code[NB];
    __shared__ unsigned char s_na[NB];
    __shared__ float s_rmax[32];
    __shared__ int   s_rmaxi[32];
    __shared__ int   s_maxidx;
    const unsigned FULL = 0xFFFFFFFFu;
    int tid = threadIdx.x;  // 1024 threads, tid == bin

    float c = 0.f;
    for (int s = 0; s < GRID_SEG; ++s) c += g_partc[s * NB + tid];
    s_cnt[tid] = c;
    float ba = c * (1.0f / (float)NROWS);  // exact (pow2 divide)
    float aem = 0.99f * assignments[tid] + 0.01f * ba;
    s_aem[tid] = aem;
    s_na[tid] = (aem * (float)NROWS) < 9.765625e-05f ? 1 : 0;  // 0.1/1024

    // argmax(batch_assign) == argmax(counts), first index on ties
    float mv = c; int mi = tid;
#pragma unroll
    for (int off = 16; off; off >>= 1) {
        float ov = __shfl_xor_sync(FULL, mv, off);
        int   oi = __shfl_xor_sync(FULL, mi, off);
        if (ov > mv || (ov == mv && oi < mi)) { mv = ov; mi = oi; }
    }
    if ((tid & 31) == 0) { s_rmax[tid >> 5] = mv; s_rmaxi[tid >> 5] = mi; }
    __syncthreads();
    if (tid == 0) {
        float m = s_rmax[0]; int midx = s_rmaxi[0];
        for (int w = 1; w < 32; w++) {
            if (s_rmax[w] > m || (s_rmax[w] == m && s_rmaxi[w] < midx)) {
                m = s_rmax[w]; midx = s_rmaxi[w];
            }
        }
        s_maxidx = midx;
    }
    __syncthreads();

    // exact sequential dead-code scan (high -> low index, as reference)
    if (tid == 0) {
        int midx = s_maxidx;
        bool maxRe = false;
        for (int i = NB - 1; i >= 0; --i) {
            if (s_na[i]) {
                float na = s_aem[midx] * 0.5f;
                s_code[i] = maxRe ? 2 : 1;  // 2: max vector already noised
                s_aem[i] = na;
                s_aem[midx] = na;
                if (i == midx) maxRe = true;
            } else {
                s_code[i] = 0;
            }
        }
    }
    __syncthreads();
    int midx = s_maxidx;

    // new_vectors
    for (int it = 0; it < 32; ++it) {
        int n = tid + it * 1024;  // 0..32767
        int b = n >> 5, d = n & 31;
        float sz = 0.f;
        for (int s = 0; s < GRID_SEG; ++s)
            sz += g_parts[(size_t)s * NB * DZ + n];
        unsigned char code = s_code[b];
        float v2;
        if (code == 0) {
            v2 = vectors[n];
        } else {
            v2 = vectors[midx * DZ + d] + noise[n];
            if (code == 2) v2 += noise[midx * DZ + d];
        }
        float cntb = s_cnt[b];
        float mean = (cntb > 0.f) ? (sz / cntb) : v2;
        out[1 + n] = 0.99f * v2 + 0.01f * mean;
    }

    // assign_ema
    out[1 + NB * DZ + tid] = s_aem[tid];

    // loss
    if (tid == 0) {
        double recon = 0.5 * (g_recon / (double)NROWS)
                     + 32.0 * 1.8378770664093453;  // 0.5*d_x*log(2*pi)
        double commit = g_commit / ((double)NROWS * (double)DZ);
        out[0] = (float)(recon + 0.25 * commit);
    }
}

// ---------------------------------------------------------------------------
extern "C" void kernel_launch(void* const* d_in, const int* in_sizes, int n_in,
                              void* d_out, int out_size) {
    const float* x           = (const float*)d_in[0];
    const float* W_enc       = (const float*)d_in[1];
    const float* b_enc       = (const float*)d_in[2];
    const float* vectors     = (const float*)d_in[3];
    const float* W_dec       = (const float*)d_in[4];
    const float* b_dec       = (const float*)d_in[5];
    const float* assignments = (const float*)d_in[6];
    const float* noise       = (const float*)d_in[7];
    float* out = (float*)d_out;

    cudaFuncSetAttribute(k_main, cudaFuncAttributeMaxDynamicSharedMemorySize,
                         SMEM_MAIN);
    cudaFuncSetAttribute(k_segsum, cudaFuncAttributeMaxDynamicSharedMemorySize,
                         SMEM_SEG);

    k_init<<<4, 256>>>(vectors);
    k_main<<<GRID_MAIN, 256, SMEM_MAIN>>>(x, W_enc, b_enc, vectors, W_dec, b_dec);
    k_segsum<<<GRID_SEG, 256, SMEM_SEG>>>();
    k_finalize<<<1, 1024>>>(vectors, assignments, noise, out);
}

// round 3
// speedup vs baseline: 1.4756x; 1.4756x over previous
#include <cuda_runtime.h>
#include <math.h>
#include <stdint.h>

typedef unsigned long long u64;

// Problem constants (fixed shapes from reference setup_inputs)
#define NROWS 262144
#define DX 64
#define DZ 32
#define NB 1024
#define TR 128                       // rows per block in main kernel
#define NCHUNK (NB / 128)            // 8 bin-chunks of 128
#define GRID_MAIN (NROWS / TR)       // 2048
#define GRID_SEG 148
#define SEG_CH ((NROWS + GRID_SEG - 1) / GRID_SEG)  // 1772

// Scratch (static device globals; no runtime allocation)
__device__ float  g_z[NROWS * DZ];            // 32 MB
__device__ int    g_idx[NROWS];               // 1 MB
__device__ float  g_hn[NB];                   // 0.5*||v_b||^2
__device__ float  g_sum[NB * DZ];             // global sum_z accumulator
__device__ float  g_cnt[NB];                  // global count accumulator
__device__ double g_recon;
__device__ double g_commit;

#define FMA2(d, a, b) asm("fma.rn.f32x2 %0, %1, %2, %0;" : "+l"(d) : "l"(a), "l"(b))

__device__ __forceinline__ void unpack2(u64 p, float& lo, float& hi) {
    asm("mov.b64 {%0,%1}, %2;" : "=f"(lo), "=f"(hi) : "l"(p));
}
__device__ __forceinline__ u64 dup2(float v) {
    u64 r; asm("mov.b64 %0, {%1,%1};" : "=l"(r) : "f"(v)); return r;
}

// ---------------------------------------------------------------------------
// init: half-norms of codebook + zero all accumulators (every graph replay)
// ---------------------------------------------------------------------------
__global__ void k_init(const float* __restrict__ vectors) {
    int t = blockIdx.x * blockDim.x + threadIdx.x;  // 0..33791
    if (t < NB) {
        float s = 0.f;
#pragma unroll
        for (int d = 0; d < DZ; ++d) {
            float v = vectors[t * DZ + d];
            s = fmaf(v, v, s);
        }
        g_hn[t] = 0.5f * s;
        g_cnt[t] = 0.f;
    }
    if (t < NB * DZ) g_sum[t] = 0.f;
    if (t == 0) { g_recon = 0.0; g_commit = 0.0; }
}

// ---------------------------------------------------------------------------
// main fused kernel: encoder -> scores/argmin (f32x2) -> gather -> decoder
// One block handles TR=128 rows. 256 threads, 2 CTAs/SM.
// ---------------------------------------------------------------------------
// shared layout (float offsets), all even (u64-aligned):
#define SM_X    0                     // [128][64]         8192
#define SM_WE   8192                  // [64][32]          2048
#define SM_WD   10240                 // [32][64]          2048
#define SM_ZT   12288                 // z^T [32][130]     4160 (pad 130)
#define SM_VT   16448                 // v^T [32][130]     4160 (pad 130)
#define SM_HN   20608                 // [128]              128
#define SM_BENC 20736                 // 32
#define SM_BDEC 20768                 // 64
#define SM_RIDX 20832                 // 128 (int)
#define SM_RED  20960                 // 16
#define SM_MAIN_FLOATS 20976
#define SMEM_MAIN (SM_MAIN_FLOATS * 4)
#define SM_Q    SM_VT                 // s_q [128][32] overlays s_vt after argmin

__global__ void __launch_bounds__(256, 2) k_main(
    const float* __restrict__ x, const float* __restrict__ W_enc,
    const float* __restrict__ b_enc, const float* __restrict__ vectors,
    const float* __restrict__ W_dec, const float* __restrict__ b_dec)
{
    extern __shared__ float sm[];
    float* s_x    = sm + SM_X;
    float* s_we   = sm + SM_WE;
    float* s_wd   = sm + SM_WD;
    float* s_zt   = sm + SM_ZT;
    float* s_vt   = sm + SM_VT;
    float* s_hn   = sm + SM_HN;
    float* s_benc = sm + SM_BENC;
    float* s_bdec = sm + SM_BDEC;
    int*   s_ridx = (int*)(sm + SM_RIDX);
    float* s_red  = sm + SM_RED;
    float* s_q    = sm + SM_Q;

    const int tid  = threadIdx.x;
    const int row0 = blockIdx.x * TR;
    const unsigned FULL = 0xFFFFFFFFu;

    // ---- load x tile + weights ----
    {
        const float4* xs = (const float4*)(x + (size_t)row0 * DX);
        float4* sx4 = (float4*)s_x;
        for (int n = tid; n < TR * DX / 4; n += 256) sx4[n] = xs[n];
        for (int n = tid; n < DX * DZ; n += 256) s_we[n] = W_enc[n];
        for (int n = tid; n < DZ * DX; n += 256) s_wd[n] = W_dec[n];
        if (tid < DZ) s_benc[tid] = b_enc[tid];
        if (tid < DX) s_bdec[tid] = b_dec[tid];
    }
    __syncthreads();

    // ---- stage 1: z = x @ W_enc + b_enc (store z^T in smem + z in gmem) ----
    {
        int col = tid & 31;
        int rb  = (tid >> 5) * 16;
        float bia = s_benc[col];
        for (int rr = 0; rr < 16; ++rr) {
            int r = rb + rr;
            float acc = bia;
#pragma unroll 16
            for (int k = 0; k < DX; ++k)
                acc = fmaf(s_x[r * DX + k], s_we[k * DZ + col], acc);
            s_zt[col * 130 + r] = acc;
            g_z[(size_t)(row0 + r) * DZ + col] = acc;
        }
    }
    __syncthreads();

    // ---- stage 2: scores + running argmax (argmin of d2), f32x2 packed ----
    // thread (rg, cg): rows rbase..rbase+7 (pairs), cols {2cg+32j', 2cg+32j'+1}
    const int rg = tid >> 4, cg = tid & 15;
    const int rbase = rg * 8;
    float best[8]; int bidx[8];
#pragma unroll
    for (int i = 0; i < 8; i++) { best[i] = -3.4e38f; bidx[i] = 0; }

    for (int ch = 0; ch < NCHUNK; ++ch) {
        // load codebook chunk transposed: s_vt[d][c]
        for (int n = tid; n < 128 * DZ; n += 256) {
            int c = n >> 5, d = n & 31;
            s_vt[d * 130 + c] = vectors[(size_t)(ch * 128 + c) * DZ + d];
        }
        if (tid < 128) s_hn[tid] = g_hn[ch * 128 + tid];
        __syncthreads();

        u64 acc2[4][8];
#pragma unroll
        for (int i = 0; i < 4; i++)
#pragma unroll
            for (int j = 0; j < 8; j++) acc2[i][j] = 0ull;

#pragma unroll 4
        for (int k = 0; k < DZ; ++k) {
            const u64* za = (const u64*)(s_zt + k * 130 + rbase);
            u64 a2[4];
#pragma unroll
            for (int i = 0; i < 4; i++) a2[i] = za[i];
            const u64* vb = (const u64*)(s_vt + k * 130 + 2 * cg);
            u64 b2[8];
#pragma unroll
            for (int jp = 0; jp < 4; ++jp) {
                float lo, hi;
                unpack2(vb[jp * 16], lo, hi);
                b2[2 * jp]     = dup2(lo);
                b2[2 * jp + 1] = dup2(hi);
            }
#pragma unroll
            for (int i = 0; i < 4; i++)
#pragma unroll
                for (int j = 0; j < 8; j++)
                    FMA2(acc2[i][j], a2[i], b2[j]);
        }

        // score = z.v - 0.5||v||^2 ; ascending col order + strict '>' keeps
        // the lowest-index max == jnp.argmin(d2) tie behavior
#pragma unroll
        for (int j = 0; j < 8; j++) {
            int col = 2 * cg + 32 * (j >> 1) + (j & 1);
            float hn = s_hn[col];
            int bin = ch * 128 + col;
#pragma unroll
            for (int i = 0; i < 4; i++) {
                float lo, hi;
                unpack2(acc2[i][j], lo, hi);
                float sc0 = lo - hn, sc1 = hi - hn;
                if (sc0 > best[2 * i])     { best[2 * i] = sc0;     bidx[2 * i] = bin; }
                if (sc1 > best[2 * i + 1]) { best[2 * i + 1] = sc1; bidx[2 * i + 1] = bin; }
            }
        }
        __syncthreads();  // protect s_vt before next chunk overwrites
    }

    // ---- reduce best across the 16 cg-threads (lanes form 16-groups) ----
#pragma unroll
    for (int i = 0; i < 8; i++) {
        float bs = best[i]; int bi = bidx[i];
#pragma unroll
        for (int off = 8; off >= 1; off >>= 1) {
            float os = __shfl_xor_sync(FULL, bs, off);
            int   oi = __shfl_xor_sync(FULL, bi, off);
            if (os > bs || (os == bs && oi < bi)) { bs = os; bi = oi; }
        }
        if (cg == 0) {
            s_ridx[rbase + i] = bi;
            g_idx[row0 + rbase + i] = bi;
        }
    }
    __syncthreads();

    // ---- gather quantized (into s_q, overlaying s_vt) + commitment ----
    float commit = 0.f;
    for (int n = tid; n < TR * DZ; n += 256) {
        int r = n >> 5, d = n & 31;
        float q = vectors[(size_t)s_ridx[r] * DZ + d];
        s_q[r * DZ + d] = q;
        float zz = s_zt[d * 130 + r];
        float df = q - zz;
        commit = fmaf(df, df, commit);
    }
    __syncthreads();  // s_q ready

    // ---- decoder mu = q @ W_dec + b_dec, reconstruction partial ----
    float recon = 0.f;
    {
        int c  = tid & 63;
        int rb = (tid >> 6) * 32;
        float wcol[DZ];
#pragma unroll
        for (int k = 0; k < DZ; k++) wcol[k] = s_wd[k * DX + c];
        float bd = s_bdec[c];
        for (int rr = 0; rr < 32; ++rr) {
            int r = rb + rr;
            float m = bd;
#pragma unroll
            for (int k = 0; k < DZ; k++)
                m = fmaf(s_q[r * DZ + k], wcol[k], m);
            float d = s_x[r * DX + c] - m;
            recon = fmaf(d, d, recon);
        }
    }

    // ---- block reduce losses -> double atomics ----
#pragma unroll
    for (int off = 16; off; off >>= 1) {
        commit += __shfl_xor_sync(FULL, commit, off);
        recon  += __shfl_xor_sync(FULL, recon, off);
    }
    int wid = tid >> 5, lid = tid & 31;
    if (lid == 0) { s_red[wid] = commit; s_red[8 + wid] = recon; }
    __syncthreads();
    if (tid == 0) {
        float cs = 0.f, rs = 0.f;
        for (int w = 0; w < 8; w++) { cs += s_red[w]; rs += s_red[8 + w]; }
        atomicAdd(&g_commit, (double)cs);
        atomicAdd(&g_recon,  (double)rs);
    }
}

// ---------------------------------------------------------------------------
// segment sum: per-SM shared-memory histogram -> global atomic merge
// ---------------------------------------------------------------------------
#define SMEM_SEG ((NB * DZ + NB) * 4)

__global__ void __launch_bounds__(256, 1) k_segsum() {
    extern __shared__ float sm[];
    float* s_sum = sm;            // [1024][32]
    float* s_cnt = sm + NB * DZ;  // [1024]
    int tid = threadIdx.x;
    for (int n = tid; n < NB * DZ + NB; n += 256) sm[n] = 0.f;
    __syncthreads();

    int start = blockIdx.x * SEG_CH;
    int end = min(NROWS, start + SEG_CH);
    int d = tid & 31, rs = tid >> 5;
    for (int r = start + rs; r < end; r += 8) {
        int b = g_idx[r];
        atomicAdd(&s_sum[b * DZ + d], g_z[(size_t)r * DZ + d]);
        if (d == 0) atomicAdd(&s_cnt[b], 1.f);
    }
    __syncthreads();
    for (int n = tid; n < NB * DZ; n += 256) {
        float v = s_sum[n];
        if (v != 0.f) atomicAdd(&g_sum[n], v);
    }
    for (int n = tid; n < NB; n += 256) {
        float v = s_cnt[n];
        if (v != 0.f) atomicAdd(&g_cnt[n], v);
    }
}

// ---------------------------------------------------------------------------
// finalize: EMA, dead-code scan (exact), write outputs
// out layout: [0]=loss, [1..32768]=new_vectors, [32769..33792]=assign_ema
// ---------------------------------------------------------------------------
__global__ void k_finalize(const float* __restrict__ vectors,
                           const float* __restrict__ assignments,
                           const float* __restrict__ noise,
                           float* __restrict__ out)
{
    __shared__ float s_cnt[NB];
    __shared__ float s_aem[NB];
    __shared__ unsigned char s_code[NB];
    __shared__ unsigned char s_na[NB];
    __shared__ float s_rmax[32];
    __shared__ int   s_rmaxi[32];
    __shared__ int   s_maxidx;
    const unsigned FULL = 0xFFFFFFFFu;
    int tid = threadIdx.x;  // 1024 threads, tid == bin

    float c = g_cnt[tid];
    s_cnt[tid] = c;
    float ba = c * (1.0f / (float)NROWS);  // exact (pow2 divide)
    float aem = 0.99f * assignments[tid] + 0.01f * ba;
    s_aem[tid] = aem;
    s_na[tid] = (aem * (float)NROWS) < 9.765625e-05f ? 1 : 0;  // 0.1/1024

    // argmax(batch_assign) == argmax(counts), first index on ties
    float mv = c; int mi = tid;
#pragma unroll
    for (int off = 16; off; off >>= 1) {
        float ov = __shfl_xor_sync(FULL, mv, off);
        int   oi = __shfl_xor_sync(FULL, mi, off);
        if (ov > mv || (ov == mv && oi < mi)) { mv = ov; mi = oi; }
    }
    if ((tid & 31) == 0) { s_rmax[tid >> 5] = mv; s_rmaxi[tid >> 5] = mi; }
    __syncthreads();
    if (tid == 0) {
        float m = s_rmax[0]; int midx = s_rmaxi[0];
        for (int w = 1; w < 32; w++) {
            if (s_rmax[w] > m || (s_rmax[w] == m && s_rmaxi[w] < midx)) {
                m = s_rmax[w]; midx = s_rmaxi[w];
            }
        }
        s_maxidx = midx;
    }
    __syncthreads();

    // exact sequential dead-code scan (high -> low index, as reference)
    if (tid == 0) {
        int midx = s_maxidx;
        bool maxRe = false;
        for (int i = NB - 1; i >= 0; --i) {
            if (s_na[i]) {
                float na = s_aem[midx] * 0.5f;
                s_code[i] = maxRe ? 2 : 1;  // 2: max vector already noised
                s_aem[i] = na;
                s_aem[midx] = na;
                if (i == midx) maxRe = true;
            } else {
                s_code[i] = 0;
            }
        }
    }
    __syncthreads();
    int midx = s_maxidx;

    // new_vectors
    for (int it = 0; it < 32; ++it) {
        int n = tid + it * 1024;  // 0..32767
        int b = n >> 5, d = n & 31;
        float sz = g_sum[n];
        unsigned char code = s_code[b];
        float v2;
        if (code == 0) {
            v2 = vectors[n];
        } else {
            v2 = vectors[midx * DZ + d] + noise[n];
            if (code == 2) v2 += noise[midx * DZ + d];
        }
        float cntb = s_cnt[b];
        float mean = (cntb > 0.f) ? (sz / cntb) : v2;
        out[1 + n] = 0.99f * v2 + 0.01f * mean;
    }

    // assign_ema
    out[1 + NB * DZ + tid] = s_aem[tid];

    // loss
    if (tid == 0) {
        double recon = 0.5 * (g_recon / (double)NROWS)
                     + 32.0 * 1.8378770664093453;  // 0.5*d_x*log(2*pi)
        double commit = g_commit / ((double)NROWS * (double)DZ);
        out[0] = (float)(recon + 0.25 * commit);
    }
}

// ---------------------------------------------------------------------------
extern "C" void kernel_launch(void* const* d_in, const int* in_sizes, int n_in,
                              void* d_out, int out_size) {
    const float* x           = (const float*)d_in[0];
    const float* W_enc       = (const float*)d_in[1];
    const float* b_enc       = (const float*)d_in[2];
    const float* vectors     = (const float*)d_in[3];
    const float* W_dec       = (const float*)d_in[4];
    const float* b_dec       = (const float*)d_in[5];
    const float* assignments = (const float*)d_in[6];
    const float* noise       = (const float*)d_in[7];
    float* out = (float*)d_out;

    cudaFuncSetAttribute(k_main, cudaFuncAttributeMaxDynamicSharedMemorySize,
                         SMEM_MAIN);
    cudaFuncSetAttribute(k_segsum, cudaFuncAttributeMaxDynamicSharedMemorySize,
                         SMEM_SEG);

    k_init<<<132, 256>>>(vectors);
    k_main<<<GRID_MAIN, 256, SMEM_MAIN>>>(x, W_enc, b_enc, vectors, W_dec, b_dec);
    k_segsum<<<GRID_SEG, 256, SMEM_SEG>>>();
    k_finalize<<<1, 1024>>>(vectors, assignments, noise, out);
}

// round 5
// speedup vs baseline: 3.0094x; 2.0395x over previous
#include <cuda_runtime.h>
#include <cuda_bf16.h>
#include <math.h>
#include <stdint.h>

typedef unsigned long long u64;
typedef unsigned int u32;

// Problem constants
#define NROWS 262144
#define DX 64
#define DZ 32
#define NB 1024
#define TR 128
#define GRID_MAIN (NROWS / TR)   // 2048
#define NCHUNK 128               // 1024 cols / 8

// Scratch globals
// B fragments in HMMA m16n8k16 register layout:
// [chunk 128][tile 4][lane 32][reg 2] u32 ; tile: 0=v_hi k0-15, 1=v_hi k16-31,
//                                            2=v_lo k0-15, 3=v_lo k16-31
__device__ u32    g_bfrag[NCHUNK * 4 * 32 * 2];   // 131 KB
__device__ float  g_hn[NB];            // 0.5*||v||^2 (fp32 exact)
__device__ float  g_sum[NB * DZ];      // global sum_z accumulator
__device__ float  g_cnt[NB];           // global count accumulator
__device__ unsigned char g_code[NB];
__device__ int    g_midx;
__device__ double g_recon;
__device__ double g_commit;

// pack two floats -> bf16x2 u32 (first element in low half)
__device__ __forceinline__ u32 pack_bf2(float f0, float f1) {
    __nv_bfloat162 h = __floats2bfloat162_rn(f0, f1);
    return *(u32*)&h;
}
__device__ __forceinline__ float bf_hi(float f) {
    return __bfloat162float(__float2bfloat16(f));
}

#define MMA_BF16(d, a, b) \
    asm volatile( \
        "mma.sync.aligned.m16n8k16.row.col.f32.bf16.bf16.f32 " \
        "{%0,%1,%2,%3},{%4,%5,%6,%7},{%8,%9},{%0,%1,%2,%3};" \
        : "+f"(d[0]), "+f"(d[1]), "+f"(d[2]), "+f"(d[3]) \
        : "r"(a[0]), "r"(a[1]), "r"(a[2]), "r"(a[3]), "r"(b[0]), "r"(b[1]))

// ---------------------------------------------------------------------------
// init: B fragments (hi/lo), hn, zero accumulators. 128x256 = 32768 threads.
// ---------------------------------------------------------------------------
__global__ void k_init(const float* __restrict__ vectors) {
    int t = blockIdx.x * blockDim.x + threadIdx.x;  // 0..32767

    if (t < NCHUNK * 4 * 32) {           // one (chunk,tile,lane) pair slot
        int lane  = t & 31;
        int tile  = (t >> 5) & 3;
        int chunk = t >> 7;
        int n  = chunk * 8 + (lane >> 2);      // codebook row (col of B)
        int tt = lane & 3;
        int kbase = (tile & 1) * 16 + 2 * tt;  // reg0 k, reg1 k+8
        const float* vr = vectors + (size_t)n * DZ;
        float a0 = vr[kbase],     a1 = vr[kbase + 1];
        float b0 = vr[kbase + 8], b1 = vr[kbase + 9];
        u32 r0, r1;
        if (tile < 2) {
            r0 = pack_bf2(a0, a1);
            r1 = pack_bf2(b0, b1);
        } else {
            r0 = pack_bf2(a0 - bf_hi(a0), a1 - bf_hi(a1));
            r1 = pack_bf2(b0 - bf_hi(b0), b1 - bf_hi(b1));
        }
        g_bfrag[t * 2]     = r0;
        g_bfrag[t * 2 + 1] = r1;
    }

    g_sum[t] = 0.f;
    if (t < NB) {
        float s = 0.f;
#pragma unroll
        for (int d = 0; d < DZ; ++d) {
            float v = vectors[t * DZ + d];
            s = fmaf(v, v, s);
        }
        g_hn[t] = 0.5f * s;
        g_cnt[t] = 0.f;
    }
    if (t == 0) { g_recon = 0.0; g_commit = 0.0; }
}

// ---------------------------------------------------------------------------
// main fused kernel: encoder(fp32) -> HMMA scores (bf16 3-term split) ->
// argmin -> gather -> segment-sum atomics -> decoder(fp32) -> losses
// 256 threads, 2 CTAs/SM.
// ---------------------------------------------------------------------------
// smem float offsets:
#define SM_X    0        // [128][64]   8192
#define SM_W    8192     // enc [64][32] then dec [32][64] overlay  2048
#define SM_ZF   10240    // z fp32 [128][32] 4096 ; reused as s_q after GEMM
#define SM_HN   14336    // [1024]
#define SM_BENC 15360    // 32
#define SM_BDEC 15392    // 64
#define SM_RIDX 15456    // 128 (int)
#define SM_RED  15584    // 16
#define SM_TOTAL_FLOATS 15600
#define SMEM_MAIN (SM_TOTAL_FLOATS * 4)
#define SM_Q SM_ZF

__global__ void __launch_bounds__(256, 2) k_main(
    const float* __restrict__ x, const float* __restrict__ W_enc,
    const float* __restrict__ b_enc, const float* __restrict__ vectors,
    const float* __restrict__ W_dec, const float* __restrict__ b_dec)
{
    extern __shared__ float sm[];
    float* s_x    = sm + SM_X;
    float* s_w    = sm + SM_W;
    float* s_zf   = sm + SM_ZF;
    float* s_hn   = sm + SM_HN;
    float* s_benc = sm + SM_BENC;
    float* s_bdec = sm + SM_BDEC;
    int*   s_ridx = (int*)(sm + SM_RIDX);
    float* s_red  = sm + SM_RED;
    float* s_q    = sm + SM_Q;

    const int tid  = threadIdx.x;
    const int wid  = tid >> 5;
    const int lane = tid & 31;
    const int row0 = blockIdx.x * TR;
    const unsigned FULL = 0xFFFFFFFFu;

    // ---- load x tile + encoder weights + hn ----
    {
        const float4* xs = (const float4*)(x + (size_t)row0 * DX);
        float4* sx4 = (float4*)s_x;
        for (int n = tid; n < TR * DX / 4; n += 256) sx4[n] = xs[n];
        for (int n = tid; n < DX * DZ; n += 256) s_w[n] = W_enc[n];
        for (int n = tid; n < NB; n += 256) s_hn[n] = g_hn[n];
        if (tid < DZ) s_benc[tid] = b_enc[tid];
        if (tid < DX) s_bdec[tid] = b_dec[tid];
    }
    __syncthreads();

    // ---- stage 1: z = x @ W_enc + b_enc (fp32 exact) ----
    const int col = tid & 31;
    const int rb  = (tid >> 5) * 16;
    float z_regs[16];
    {
        float bia = s_benc[col];
#pragma unroll
        for (int g = 0; g < 4; ++g) {
            float a0 = bia, a1 = bia, a2 = bia, a3 = bia;
            const float* x0 = s_x + (rb + g * 4 + 0) * DX;
            const float* x1 = s_x + (rb + g * 4 + 1) * DX;
            const float* x2 = s_x + (rb + g * 4 + 2) * DX;
            const float* x3 = s_x + (rb + g * 4 + 3) * DX;
#pragma unroll 16
            for (int k = 0; k < DX; ++k) {
                float w = s_w[k * DZ + col];
                a0 = fmaf(x0[k], w, a0);
                a1 = fmaf(x1[k], w, a1);
                a2 = fmaf(x2[k], w, a2);
                a3 = fmaf(x3[k], w, a3);
            }
            z_regs[g * 4 + 0] = a0; z_regs[g * 4 + 1] = a1;
            z_regs[g * 4 + 2] = a2; z_regs[g * 4 + 3] = a3;
            s_zf[(rb + g * 4 + 0) * DZ + col] = a0;
            s_zf[(rb + g * 4 + 1) * DZ + col] = a1;
            s_zf[(rb + g * 4 + 2) * DZ + col] = a2;
            s_zf[(rb + g * 4 + 3) * DZ + col] = a3;
        }
    }
    __syncthreads();

    // ---- stage 2: build A fragments (hi/lo) for this warp's 16 rows ----
    const int g4 = lane >> 2, t4 = lane & 3;
    const int r0 = wid * 16 + g4, r1 = r0 + 8;
    u32 Ahi[2][4], Alo[2][4];
#pragma unroll
    for (int kt = 0; kt < 2; ++kt) {
        int kb = kt * 16 + 2 * t4;
        float z00 = s_zf[r0 * DZ + kb],     z01 = s_zf[r0 * DZ + kb + 1];
        float z10 = s_zf[r1 * DZ + kb],     z11 = s_zf[r1 * DZ + kb + 1];
        float z02 = s_zf[r0 * DZ + kb + 8], z03 = s_zf[r0 * DZ + kb + 9];
        float z12 = s_zf[r1 * DZ + kb + 8], z13 = s_zf[r1 * DZ + kb + 9];
        Ahi[kt][0] = pack_bf2(z00, z01);
        Ahi[kt][1] = pack_bf2(z10, z11);
        Ahi[kt][2] = pack_bf2(z02, z03);
        Ahi[kt][3] = pack_bf2(z12, z13);
        Alo[kt][0] = pack_bf2(z00 - bf_hi(z00), z01 - bf_hi(z01));
        Alo[kt][1] = pack_bf2(z10 - bf_hi(z10), z11 - bf_hi(z11));
        Alo[kt][2] = pack_bf2(z02 - bf_hi(z02), z03 - bf_hi(z03));
        Alo[kt][3] = pack_bf2(z12 - bf_hi(z12), z13 - bf_hi(z13));
    }

    // ---- stage 3: HMMA over 128 col-chunks, running argmax ----
    float best0 = -3.4e38f, best1 = -3.4e38f;
    int   bi0 = 0, bi1 = 0;
    const uint2* bsrc = (const uint2*)g_bfrag + lane;

#pragma unroll 2
    for (int c = 0; c < NCHUNK; ++c) {
        const uint2* bp = bsrc + c * 128;
        uint2 t0 = bp[0];        // v_hi k0-15
        uint2 t1 = bp[32];       // v_hi k16-31
        uint2 t2 = bp[64];       // v_lo k0-15
        uint2 t3 = bp[96];       // v_lo k16-31
        u32 B0[2] = {t0.x, t0.y};
        u32 B1[2] = {t1.x, t1.y};
        u32 B2[2] = {t2.x, t2.y};
        u32 B3[2] = {t3.x, t3.y};

        float d[4] = {0.f, 0.f, 0.f, 0.f};
        MMA_BF16(d, Ahi[0], B0);
        MMA_BF16(d, Ahi[1], B1);
        MMA_BF16(d, Ahi[0], B2);
        MMA_BF16(d, Ahi[1], B3);
        MMA_BF16(d, Alo[0], B0);
        MMA_BF16(d, Alo[1], B1);

        int col0 = c * 8 + 2 * t4;
        float2 hn = *(const float2*)(s_hn + col0);
        // rows: d0,d1 -> r0 ; d2,d3 -> r1 ; ascending col within thread,
        // strict '>' keeps lowest index on ties
        float s0 = d[0] - hn.x, s1 = d[1] - hn.y;
        float s2 = d[2] - hn.x, s3 = d[3] - hn.y;
        if (s0 > best0) { best0 = s0; bi0 = col0; }
        if (s1 > best0) { best0 = s1; bi0 = col0 + 1; }
        if (s2 > best1) { best1 = s2; bi1 = col0; }
        if (s3 > best1) { best1 = s3; bi1 = col0 + 1; }
    }

    // ---- quad reduce (lanes sharing the same rows), lowest index on ties --
#pragma unroll
    for (int off = 1; off <= 2; off <<= 1) {
        float ob0 = __shfl_xor_sync(FULL, best0, off);
        int   oi0 = __shfl_xor_sync(FULL, bi0, off);
        if (ob0 > best0 || (ob0 == best0 && oi0 < bi0)) { best0 = ob0; bi0 = oi0; }
        float ob1 = __shfl_xor_sync(FULL, best1, off);
        int   oi1 = __shfl_xor_sync(FULL, bi1, off);
        if (ob1 > best1 || (ob1 == best1 && oi1 < bi1)) { best1 = ob1; bi1 = oi1; }
    }
    if (t4 == 0) { s_ridx[r0] = bi0; s_ridx[r1] = bi1; }

    // load decoder weights (overlay s_w; encoder done)
    for (int n = tid; n < DZ * DX; n += 256) s_w[n] = W_dec[n];
    __syncthreads();

    // ---- gather q + commitment + segment-sum atomics (exact fp32 z) ----
    float commit = 0.f;
    {
#pragma unroll
        for (int rr = 0; rr < 16; ++rr) {
            int r = rb + rr;
            int b = s_ridx[r];
            float zz = z_regs[rr];
            float q = vectors[(size_t)b * DZ + col];
            s_q[r * DZ + col] = q;       // overlays s_zf (no longer read)
            float df = q - zz;
            commit = fmaf(df, df, commit);
            atomicAdd(&g_sum[b * DZ + col], zz);
            if (col == 0) atomicAdd(&g_cnt[b], 1.f);
        }
    }
    __syncthreads();  // s_q complete

    // ---- decoder mu = q @ W_dec + b_dec, reconstruction partial ----
    float recon = 0.f;
    {
        int c   = tid & 63;
        int rb2 = (tid >> 6) * 32;
        float wcol[DZ];
#pragma unroll
        for (int k = 0; k < DZ; k++) wcol[k] = s_w[k * DX + c];
        float bd = s_bdec[c];
        for (int rr = 0; rr < 32; rr += 2) {
            int r = rb2 + rr;
            float m0 = bd, m1 = bd;
#pragma unroll
            for (int k = 0; k < DZ; k++) {
                m0 = fmaf(s_q[r * DZ + k], wcol[k], m0);
                m1 = fmaf(s_q[(r + 1) * DZ + k], wcol[k], m1);
            }
            float d0 = s_x[r * DX + c] - m0;
            float d1 = s_x[(r + 1) * DX + c] - m1;
            recon = fmaf(d0, d0, recon);
            recon = fmaf(d1, d1, recon);
        }
    }

    // ---- block reduce losses -> double atomics ----
#pragma unroll
    for (int off = 16; off; off >>= 1) {
        commit += __shfl_xor_sync(FULL, commit, off);
        recon  += __shfl_xor_sync(FULL, recon, off);
    }
    if (lane == 0) { s_red[wid] = commit; s_red[8 + wid] = recon; }
    __syncthreads();
    if (tid == 0) {
        float cs = 0.f, rs = 0.f;
        for (int w = 0; w < 8; w++) { cs += s_red[w]; rs += s_red[8 + w]; }
        atomicAdd(&g_commit, (double)cs);
        atomicAdd(&g_recon,  (double)rs);
    }
}

// ---------------------------------------------------------------------------
// final1: aem, argmax, exact sequential dead-code scan; loss + aem outputs
// ---------------------------------------------------------------------------
__global__ void k_final1(const float* __restrict__ assignments,
                         float* __restrict__ out)
{
    __shared__ float s_aem[NB];
    __shared__ unsigned char s_na[NB];
    __shared__ unsigned char s_code[NB];
    __shared__ float s_rmax[32];
    __shared__ int   s_rmaxi[32];
    __shared__ int   s_maxidx;
    const unsigned FULL = 0xFFFFFFFFu;
    int tid = threadIdx.x;  // 1024 threads, tid == bin

    float c = g_cnt[tid];
    float ba = c * (1.0f / (float)NROWS);
    float aem = 0.99f * assignments[tid] + 0.01f * ba;
    s_aem[tid] = aem;
    s_na[tid] = (aem * (float)NROWS) < 9.765625e-05f ? 1 : 0;

    float mv = c; int mi = tid;
#pragma unroll
    for (int off = 16; off; off >>= 1) {
        float ov = __shfl_xor_sync(FULL, mv, off);
        int   oi = __shfl_xor_sync(FULL, mi, off);
        if (ov > mv || (ov == mv && oi < mi)) { mv = ov; mi = oi; }
    }
    if ((tid & 31) == 0) { s_rmax[tid >> 5] = mv; s_rmaxi[tid >> 5] = mi; }
    __syncthreads();
    if (tid == 0) {
        float m = s_rmax[0]; int midx = s_rmaxi[0];
        for (int w = 1; w < 32; w++) {
            if (s_rmax[w] > m || (s_rmax[w] == m && s_rmaxi[w] < midx)) {
                m = s_rmax[w]; midx = s_rmaxi[w];
            }
        }
        s_maxidx = midx;
        g_midx = midx;
    }
    __syncthreads();

    if (tid == 0) {
        int midx = s_maxidx;
        bool maxRe = false;
        for (int i = NB - 1; i >= 0; --i) {
            if (s_na[i]) {
                float na = s_aem[midx] * 0.5f;
                s_code[i] = maxRe ? 2 : 1;
                s_aem[i] = na;
                s_aem[midx] = na;
                if (i == midx) maxRe = true;
            } else {
                s_code[i] = 0;
            }
        }
    }
    __syncthreads();

    g_code[tid] = s_code[tid];
    out[1 + NB * DZ + tid] = s_aem[tid];

    if (tid == 0) {
        double recon = 0.5 * (g_recon / (double)NROWS)
                     + 32.0 * 1.8378770664093453;   // 0.5*d_x*log(2*pi)
        double commit = g_commit / ((double)NROWS * (double)DZ);
        out[0] = (float)(recon + 0.25 * commit);
    }
}

// ---------------------------------------------------------------------------
// final2: new_vectors (parallel, 32 blocks x 1024)
// ---------------------------------------------------------------------------
__global__ void k_final2(const float* __restrict__ vectors,
                         const float* __restrict__ noise,
                         float* __restrict__ out)
{
    int n = blockIdx.x * 1024 + threadIdx.x;  // 0..32767
    int b = n >> 5, d = n & 31;
    int midx = g_midx;
    float sz = g_sum[n];
    unsigned char code = g_code[b];
    float v2;
    if (code == 0) {
        v2 = vectors[n];
    } else {
        v2 = vectors[midx * DZ + d] + noise[n];
        if (code == 2) v2 += noise[midx * DZ + d];
    }
    float cntb = g_cnt[b];
    float mean = (cntb > 0.f) ? (sz / cntb) : v2;
    out[1 + n] = 0.99f * v2 + 0.01f * mean;
}

// ---------------------------------------------------------------------------
extern "C" void kernel_launch(void* const* d_in, const int* in_sizes, int n_in,
                              void* d_out, int out_size) {
    const float* x           = (const float*)d_in[0];
    const float* W_enc       = (const float*)d_in[1];
    const float* b_enc       = (const float*)d_in[2];
    const float* vectors     = (const float*)d_in[3];
    const float* W_dec       = (const float*)d_in[4];
    const float* b_dec       = (const float*)d_in[5];
    const float* assignments = (const float*)d_in[6];
    const float* noise       = (const float*)d_in[7];
    float* out = (float*)d_out;

    cudaFuncSetAttribute(k_main, cudaFuncAttributeMaxDynamicSharedMemorySize,
                         SMEM_MAIN);

    k_init<<<128, 256>>>(vectors);
    k_main<<<GRID_MAIN, 256, SMEM_MAIN>>>(x, W_enc, b_enc, vectors, W_dec, b_dec);
    k_final1<<<1, 1024>>>(assignments, out);
    k_final2<<<32, 1024>>>(vectors, noise, out);
}

// round 6
// speedup vs baseline: 3.7743x; 1.2542x over previous
#include <cuda_runtime.h>
#include <cuda_bf16.h>
#include <math.h>
#include <stdint.h>

typedef unsigned long long u64;
typedef unsigned int u32;

// Problem constants
#define NROWS 262144
#define DX 64
#define DZ 32
#define NB 1024
#define TR 128
#define GRID_MAIN (NROWS / TR)   // 2048
#define NCHUNK 128               // 1024 cols / 8

// Scratch globals
// B fragments in HMMA m16n8k16 register layout:
// [chunk 128][tile 4][lane 32][reg 2] u32 ; tile: 0=v_hi k0-15, 1=v_hi k16-31,
//                                            2=v_lo k0-15, 3=v_lo k16-31
__device__ u32    g_bfrag[NCHUNK * 4 * 32 * 2];   // 131 KB
__device__ float  g_hn[NB];            // 0.5*||v||^2 (fp32 exact)
__device__ float  g_sum[NB * DZ];      // global sum_z accumulator
__device__ float  g_cnt[NB];           // global count accumulator
__device__ unsigned char g_code[NB];
__device__ int    g_midx;
__device__ double g_recon;
__device__ double g_commit;

// pack two floats -> bf16x2 u32 (first element in low half)
__device__ __forceinline__ u32 pack_bf2(float f0, float f1) {
    __nv_bfloat162 h = __floats2bfloat162_rn(f0, f1);
    return *(u32*)&h;
}
__device__ __forceinline__ float bf_hi(float f) {
    return __bfloat162float(__float2bfloat16(f));
}

#define MMA_BF16(d, a, b) \
    asm volatile( \
        "mma.sync.aligned.m16n8k16.row.col.f32.bf16.bf16.f32 " \
        "{%0,%1,%2,%3},{%4,%5,%6,%7},{%8,%9},{%0,%1,%2,%3};" \
        : "+f"(d[0]), "+f"(d[1]), "+f"(d[2]), "+f"(d[3]) \
        : "r"(a[0]), "r"(a[1]), "r"(a[2]), "r"(a[3]), "r"(b[0]), "r"(b[1]))

// ---------------------------------------------------------------------------
// init: B fragments (hi/lo), hn, zero accumulators. 128x256 = 32768 threads.
// ---------------------------------------------------------------------------
__global__ void k_init(const float* __restrict__ vectors) {
    int t = blockIdx.x * blockDim.x + threadIdx.x;  // 0..32767

    if (t < NCHUNK * 4 * 32) {           // one (chunk,tile,lane) pair slot
        int lane  = t & 31;
        int tile  = (t >> 5) & 3;
        int chunk = t >> 7;
        int n  = chunk * 8 + (lane >> 2);      // codebook row (col of B)
        int tt = lane & 3;
        int kbase = (tile & 1) * 16 + 2 * tt;  // reg0 k, reg1 k+8
        const float* vr = vectors + (size_t)n * DZ;
        float a0 = vr[kbase],     a1 = vr[kbase + 1];
        float b0 = vr[kbase + 8], b1 = vr[kbase + 9];
        u32 r0, r1;
        if (tile < 2) {
            r0 = pack_bf2(a0, a1);
            r1 = pack_bf2(b0, b1);
        } else {
            r0 = pack_bf2(a0 - bf_hi(a0), a1 - bf_hi(a1));
            r1 = pack_bf2(b0 - bf_hi(b0), b1 - bf_hi(b1));
        }
        g_bfrag[t * 2]     = r0;
        g_bfrag[t * 2 + 1] = r1;
    }

    g_sum[t] = 0.f;
    if (t < NB) {
        float s = 0.f;
#pragma unroll
        for (int d = 0; d < DZ; ++d) {
            float v = vectors[t * DZ + d];
            s = fmaf(v, v, s);
        }
        g_hn[t] = 0.5f * s;
        g_cnt[t] = 0.f;
    }
    if (t == 0) { g_recon = 0.0; g_commit = 0.0; }
}

// ---------------------------------------------------------------------------
// main fused kernel: encoder(fp32) -> HMMA scores (bf16 3-term split) ->
// argmin -> gather -> segment-sum atomics -> decoder(fp32) -> losses
// 256 threads, 3 CTAs/SM.
// ---------------------------------------------------------------------------
// smem float offsets:
#define SM_X    0        // [128][64]   8192
#define SM_W    8192     // enc [64][32] then dec [32][64] overlay  2048
#define SM_ZF   10240    // z fp32 [128][32] 4096 ; reused as s_q after GEMM
#define SM_HN   14336    // [1024]
#define SM_BENC 15360    // 32
#define SM_BDEC 15392    // 64
#define SM_RIDX 15456    // 128 (int)
#define SM_RED  15584    // 16
#define SM_TOTAL_FLOATS 15600
#define SMEM_MAIN (SM_TOTAL_FLOATS * 4)
#define SM_Q SM_ZF

__global__ void __launch_bounds__(256, 3) k_main(
    const float* __restrict__ x, const float* __restrict__ W_enc,
    const float* __restrict__ b_enc, const float* __restrict__ vectors,
    const float* __restrict__ W_dec, const float* __restrict__ b_dec)
{
    extern __shared__ float sm[];
    float* s_x    = sm + SM_X;
    float* s_w    = sm + SM_W;
    float* s_zf   = sm + SM_ZF;
    float* s_hn   = sm + SM_HN;
    float* s_benc = sm + SM_BENC;
    float* s_bdec = sm + SM_BDEC;
    int*   s_ridx = (int*)(sm + SM_RIDX);
    float* s_red  = sm + SM_RED;
    float* s_q    = sm + SM_Q;

    const int tid  = threadIdx.x;
    const int wid  = tid >> 5;
    const int lane = tid & 31;
    const int row0 = blockIdx.x * TR;
    const unsigned FULL = 0xFFFFFFFFu;

    // ---- load x tile + encoder weights + hn ----
    {
        const float4* xs = (const float4*)(x + (size_t)row0 * DX);
        float4* sx4 = (float4*)s_x;
        for (int n = tid; n < TR * DX / 4; n += 256) sx4[n] = xs[n];
        for (int n = tid; n < DX * DZ; n += 256) s_w[n] = W_enc[n];
        for (int n = tid; n < NB; n += 256) s_hn[n] = g_hn[n];
        if (tid < DZ) s_benc[tid] = b_enc[tid];
        if (tid < DX) s_bdec[tid] = b_dec[tid];
    }
    __syncthreads();

    // ---- stage 1: z = x @ W_enc + b_enc (fp32 exact) ----
    const int col = tid & 31;
    const int rb  = (tid >> 5) * 16;
    {
        float bia = s_benc[col];
#pragma unroll
        for (int g = 0; g < 4; ++g) {
            float a0 = bia, a1 = bia, a2 = bia, a3 = bia;
            const float* x0 = s_x + (rb + g * 4 + 0) * DX;
            const float* x1 = s_x + (rb + g * 4 + 1) * DX;
            const float* x2 = s_x + (rb + g * 4 + 2) * DX;
            const float* x3 = s_x + (rb + g * 4 + 3) * DX;
#pragma unroll 16
            for (int k = 0; k < DX; ++k) {
                float w = s_w[k * DZ + col];
                a0 = fmaf(x0[k], w, a0);
                a1 = fmaf(x1[k], w, a1);
                a2 = fmaf(x2[k], w, a2);
                a3 = fmaf(x3[k], w, a3);
            }
            s_zf[(rb + g * 4 + 0) * DZ + col] = a0;
            s_zf[(rb + g * 4 + 1) * DZ + col] = a1;
            s_zf[(rb + g * 4 + 2) * DZ + col] = a2;
            s_zf[(rb + g * 4 + 3) * DZ + col] = a3;
        }
    }
    __syncthreads();

    // ---- stage 2: build A fragments (hi/lo) for this warp's 16 rows ----
    const int g4 = lane >> 2, t4 = lane & 3;
    const int r0 = wid * 16 + g4, r1 = r0 + 8;
    u32 Ahi[2][4], Alo[2][4];
#pragma unroll
    for (int kt = 0; kt < 2; ++kt) {
        int kb = kt * 16 + 2 * t4;
        float z00 = s_zf[r0 * DZ + kb],     z01 = s_zf[r0 * DZ + kb + 1];
        float z10 = s_zf[r1 * DZ + kb],     z11 = s_zf[r1 * DZ + kb + 1];
        float z02 = s_zf[r0 * DZ + kb + 8], z03 = s_zf[r0 * DZ + kb + 9];
        float z12 = s_zf[r1 * DZ + kb + 8], z13 = s_zf[r1 * DZ + kb + 9];
        Ahi[kt][0] = pack_bf2(z00, z01);
        Ahi[kt][1] = pack_bf2(z10, z11);
        Ahi[kt][2] = pack_bf2(z02, z03);
        Ahi[kt][3] = pack_bf2(z12, z13);
        Alo[kt][0] = pack_bf2(z00 - bf_hi(z00), z01 - bf_hi(z01));
        Alo[kt][1] = pack_bf2(z10 - bf_hi(z10), z11 - bf_hi(z11));
        Alo[kt][2] = pack_bf2(z02 - bf_hi(z02), z03 - bf_hi(z03));
        Alo[kt][3] = pack_bf2(z12 - bf_hi(z12), z13 - bf_hi(z13));
    }

    // ---- stage 3: HMMA over 128 col-chunks, running argmax ----
    // prefetched B (chunk c+1 loads issue before chunk c's MMAs retire)
    float best0 = -3.4e38f, best1 = -3.4e38f;
    int   bi0 = 0, bi1 = 0;
    const uint2* bsrc = (const uint2*)g_bfrag + lane;

    uint2 n0 = bsrc[0], n1 = bsrc[32], n2 = bsrc[64], n3 = bsrc[96];

#pragma unroll 2
    for (int c = 0; c < NCHUNK; ++c) {
        u32 B0[2] = {n0.x, n0.y};
        u32 B1[2] = {n1.x, n1.y};
        u32 B2[2] = {n2.x, n2.y};
        u32 B3[2] = {n3.x, n3.y};
        if (c + 1 < NCHUNK) {
            const uint2* np = bsrc + (c + 1) * 128;
            n0 = np[0]; n1 = np[32]; n2 = np[64]; n3 = np[96];
        }

        // two independent accumulation chains (3 MMAs each)
        float da[4] = {0.f, 0.f, 0.f, 0.f};
        float db[4] = {0.f, 0.f, 0.f, 0.f};
        MMA_BF16(da, Ahi[0], B0);   // z_hi . v_hi (k0-15)
        MMA_BF16(db, Ahi[1], B1);   // z_hi . v_hi (k16-31)
        MMA_BF16(da, Ahi[0], B2);   // z_hi . v_lo (k0-15)
        MMA_BF16(db, Ahi[1], B3);   // z_hi . v_lo (k16-31)
        MMA_BF16(da, Alo[0], B0);   // z_lo . v_hi (k0-15)
        MMA_BF16(db, Alo[1], B1);   // z_lo . v_hi (k16-31)

        int col0 = c * 8 + 2 * t4;
        float2 hn = *(const float2*)(s_hn + col0);
        float s0 = (da[0] + db[0]) - hn.x;
        float s1 = (da[1] + db[1]) - hn.y;
        float s2 = (da[2] + db[2]) - hn.x;
        float s3 = (da[3] + db[3]) - hn.y;

        // merge the 2 candidates per row first (strict '>' keeps lower idx),
        // then one best-update per row per chunk
        bool c0 = s1 > s0;
        float v0 = c0 ? s1 : s0; int i0 = col0 + (int)c0;
        bool c1 = s3 > s2;
        float v1 = c1 ? s3 : s2; int i1 = col0 + (int)c1;
        if (v0 > best0) { best0 = v0; bi0 = i0; }
        if (v1 > best1) { best1 = v1; bi1 = i1; }
    }

    // ---- quad reduce (lanes sharing the same rows), lowest index on ties --
#pragma unroll
    for (int off = 1; off <= 2; off <<= 1) {
        float ob0 = __shfl_xor_sync(FULL, best0, off);
        int   oi0 = __shfl_xor_sync(FULL, bi0, off);
        if (ob0 > best0 || (ob0 == best0 && oi0 < bi0)) { best0 = ob0; bi0 = oi0; }
        float ob1 = __shfl_xor_sync(FULL, best1, off);
        int   oi1 = __shfl_xor_sync(FULL, bi1, off);
        if (ob1 > best1 || (ob1 == best1 && oi1 < bi1)) { best1 = ob1; bi1 = oi1; }
    }
    if (t4 == 0) { s_ridx[r0] = bi0; s_ridx[r1] = bi1; }

    // load decoder weights (overlay s_w; encoder done)
    for (int n = tid; n < DZ * DX; n += 256) s_w[n] = W_dec[n];
    __syncthreads();

    // ---- gather q + commitment + segment-sum atomics (exact fp32 z) ----
    // each element read (s_zf) then overwritten (s_q) by the same thread
    float commit = 0.f;
    {
#pragma unroll
        for (int rr = 0; rr < 16; ++rr) {
            int r = rb + rr;
            int b = s_ridx[r];
            float zz = s_zf[r * DZ + col];
            float q = vectors[(size_t)b * DZ + col];
            s_q[r * DZ + col] = q;
            float df = q - zz;
            commit = fmaf(df, df, commit);
            atomicAdd(&g_sum[b * DZ + col], zz);
            if (col == 0) atomicAdd(&g_cnt[b], 1.f);
        }
    }
    __syncthreads();  // s_q complete

    // ---- decoder mu = q @ W_dec + b_dec, reconstruction partial ----
    float recon = 0.f;
    {
        int c   = tid & 63;
        int rb2 = (tid >> 6) * 32;
        float wcol[DZ];
#pragma unroll
        for (int k = 0; k < DZ; k++) wcol[k] = s_w[k * DX + c];
        float bd = s_bdec[c];
        for (int rr = 0; rr < 32; rr += 2) {
            int r = rb2 + rr;
            float m0 = bd, m1 = bd;
#pragma unroll
            for (int k = 0; k < DZ; k++) {
                m0 = fmaf(s_q[r * DZ + k], wcol[k], m0);
                m1 = fmaf(s_q[(r + 1) * DZ + k], wcol[k], m1);
            }
            float d0 = s_x[r * DX + c] - m0;
            float d1 = s_x[(r + 1) * DX + c] - m1;
            recon = fmaf(d0, d0, recon);
            recon = fmaf(d1, d1, recon);
        }
    }

    // ---- block reduce losses -> double atomics ----
#pragma unroll
    for (int off = 16; off; off >>= 1) {
        commit += __shfl_xor_sync(FULL, commit, off);
        recon  += __shfl_xor_sync(FULL, recon, off);
    }
    if (lane == 0) { s_red[wid] = commit; s_red[8 + wid] = recon; }
    __syncthreads();
    if (tid == 0) {
        float cs = 0.f, rs = 0.f;
        for (int w = 0; w < 8; w++) { cs += s_red[w]; rs += s_red[8 + w]; }
        atomicAdd(&g_commit, (double)cs);
        atomicAdd(&g_recon,  (double)rs);
    }
}

// ---------------------------------------------------------------------------
// final1: aem, argmax, dead-code scan (skipped when no dead bins; exact
// sequential fallback otherwise); loss + aem outputs
// ---------------------------------------------------------------------------
__global__ void k_final1(const float* __restrict__ assignments,
                         float* __restrict__ out)
{
    __shared__ float s_aem[NB];
    __shared__ unsigned char s_na[NB];
    __shared__ unsigned char s_code[NB];
    __shared__ float s_rmax[32];
    __shared__ int   s_rmaxi[32];
    __shared__ int   s_maxidx;
    const unsigned FULL = 0xFFFFFFFFu;
    int tid = threadIdx.x;  // 1024 threads, tid == bin

    float c = g_cnt[tid];
    float ba = c * (1.0f / (float)NROWS);
    float aem = 0.99f * assignments[tid] + 0.01f * ba;
    s_aem[tid] = aem;
    int na = (aem * (float)NROWS) < 9.765625e-05f ? 1 : 0;
    s_na[tid] = (unsigned char)na;
    s_code[tid] = 0;

    float mv = c; int mi = tid;
#pragma unroll
    for (int off = 16; off; off >>= 1) {
        float ov = __shfl_xor_sync(FULL, mv, off);
        int   oi = __shfl_xor_sync(FULL, mi, off);
        if (ov > mv || (ov == mv && oi < mi)) { mv = ov; mi = oi; }
    }
    if ((tid & 31) == 0) { s_rmax[tid >> 5] = mv; s_rmaxi[tid >> 5] = mi; }
    int any_na = __syncthreads_or(na);
    if (tid == 0) {
        float m = s_rmax[0]; int midx = s_rmaxi[0];
        for (int w = 1; w < 32; w++) {
            if (s_rmax[w] > m || (s_rmax[w] == m && s_rmaxi[w] < midx)) {
                m = s_rmax[w]; midx = s_rmaxi[w];
            }
        }
        s_maxidx = midx;
        g_midx = midx;
    }
    __syncthreads();

    if (any_na) {
        if (tid == 0) {
            int midx = s_maxidx;
            bool maxRe = false;
            for (int i = NB - 1; i >= 0; --i) {
                if (s_na[i]) {
                    float na2 = s_aem[midx] * 0.5f;
                    s_code[i] = maxRe ? 2 : 1;
                    s_aem[i] = na2;
                    s_aem[midx] = na2;
                    if (i == midx) maxRe = true;
                }
            }
        }
        __syncthreads();
    }

    g_code[tid] = s_code[tid];
    out[1 + NB * DZ + tid] = s_aem[tid];

    if (tid == 0) {
        double recon = 0.5 * (g_recon / (double)NROWS)
                     + 32.0 * 1.8378770664093453;   // 0.5*d_x*log(2*pi)
        double commit = g_commit / ((double)NROWS * (double)DZ);
        out[0] = (float)(recon + 0.25 * commit);
    }
}

// ---------------------------------------------------------------------------
// final2: new_vectors (parallel, 32 blocks x 1024)
// ---------------------------------------------------------------------------
__global__ void k_final2(const float* __restrict__ vectors,
                         const float* __restrict__ noise,
                         float* __restrict__ out)
{
    int n = blockIdx.x * 1024 + threadIdx.x;  // 0..32767
    int b = n >> 5, d = n & 31;
    int midx = g_midx;
    float sz = g_sum[n];
    unsigned char code = g_code[b];
    float v2;
    if (code == 0) {
        v2 = vectors[n];
    } else {
        v2 = vectors[midx * DZ + d] + noise[n];
        if (code == 2) v2 += noise[midx * DZ + d];
    }
    float cntb = g_cnt[b];
    float mean = (cntb > 0.f) ? (sz / cntb) : v2;
    out[1 + n] = 0.99f * v2 + 0.01f * mean;
}

// ---------------------------------------------------------------------------
extern "C" void kernel_launch(void* const* d_in, const int* in_sizes, int n_in,
                              void* d_out, int out_size) {
    const float* x           = (const float*)d_in[0];
    const float* W_enc       = (const float*)d_in[1];
    const float* b_enc       = (const float*)d_in[2];
    const float* vectors     = (const float*)d_in[3];
    const float* W_dec       = (const float*)d_in[4];
    const float* b_dec       = (const float*)d_in[5];
    const float* assignments = (const float*)d_in[6];
    const float* noise       = (const float*)d_in[7];
    float* out = (float*)d_out;

    cudaFuncSetAttribute(k_main, cudaFuncAttributeMaxDynamicSharedMemorySize,
                         SMEM_MAIN);

    k_init<<<128, 256>>>(vectors);
    k_main<<<GRID_MAIN, 256, SMEM_MAIN>>>(x, W_enc, b_enc, vectors, W_dec, b_dec);
    k_final1<<<1, 1024>>>(assignments, out);
    k_final2<<<32, 1024>>>(vectors, noise, out);
}

// round 7
// speedup vs baseline: 4.5928x; 1.2168x over previous
#include <cuda_runtime.h>
#include <cuda_bf16.h>
#include <math.h>
#include <stdint.h>

typedef unsigned long long u64;
typedef unsigned int u32;

// Problem constants
#define NROWS 262144
#define DX 64
#define DZ 32
#define NB 1024
#define TR 128
#define GRID_MAIN (NROWS / TR)   // 2048
#define NCHUNK 128               // 1024 cols / 8
#define SXP 68                   // s_x row stride (floats)
#define SZP 34                   // s_zf row stride (floats)

// Scratch globals
// Codebook B fragments (HMMA m16n8k16 layout):
// [chunk 128][tile 4][lane 32][reg 2]; tile: 0=v_hi k0-15, 1=v_hi k16-31,
//                                            2=v_lo k0-15, 3=v_lo k16-31
__device__ u32    g_bfrag[NCHUNK * 4 * 32 * 2];   // 131 KB
// W_enc fragments: [(kt*4+nt)*2+term][lane] ; term 0=hi 1=lo
__device__ uint2  g_wef[4 * 4 * 2 * 32];
// W_dec fragments: [(kt*8+nt)*2+term][lane]
__device__ uint2  g_wdf[2 * 8 * 2 * 32];
__device__ float  g_hn[NB];            // 0.5*||v||^2 (fp32 exact)
__device__ float  g_sum[NB * DZ];      // global sum_z accumulator
__device__ float  g_cnt[NB];           // global count accumulator
__device__ unsigned char g_code[NB];
__device__ int    g_midx;
__device__ double g_recon;
__device__ double g_commit;

__device__ __forceinline__ u32 pack_bf2(float f0, float f1) {
    __nv_bfloat162 h = __floats2bfloat162_rn(f0, f1);
    return *(u32*)&h;
}
__device__ __forceinline__ float bf_hi(float f) {
    return __bfloat162float(__float2bfloat16(f));
}
__device__ __forceinline__ u32 pack_lo2(float f0, float f1) {
    return pack_bf2(f0 - bf_hi(f0), f1 - bf_hi(f1));
}

#define MMA_BF16(d, a, b) \
    asm volatile( \
        "mma.sync.aligned.m16n8k16.row.col.f32.bf16.bf16.f32 " \
        "{%0,%1,%2,%3},{%4,%5,%6,%7},{%8,%9},{%0,%1,%2,%3};" \
        : "+f"(d[0]), "+f"(d[1]), "+f"(d[2]), "+f"(d[3]) \
        : "r"(a[0]), "r"(a[1]), "r"(a[2]), "r"(a[3]), "r"(b[0]), "r"(b[1]))

// ---------------------------------------------------------------------------
// init: codebook/W fragments (hi/lo), hn, zero accumulators. 32768 threads.
// ---------------------------------------------------------------------------
__global__ void k_init(const float* __restrict__ vectors,
                       const float* __restrict__ W_enc,
                       const float* __restrict__ W_dec) {
    int t = blockIdx.x * blockDim.x + threadIdx.x;  // 0..32767

    if (t < NCHUNK * 4 * 32) {           // codebook fragment slot
        int lane  = t & 31;
        int tile  = (t >> 5) & 3;
        int chunk = t >> 7;
        int n  = chunk * 8 + (lane >> 2);
        int tt = lane & 3;
        int kbase = (tile & 1) * 16 + 2 * tt;
        const float* vr = vectors + (size_t)n * DZ;
        float a0 = vr[kbase],     a1 = vr[kbase + 1];
        float b0 = vr[kbase + 8], b1 = vr[kbase + 9];
        u32 r0, r1;
        if (tile < 2) { r0 = pack_bf2(a0, a1); r1 = pack_bf2(b0, b1); }
        else          { r0 = pack_lo2(a0, a1); r1 = pack_lo2(b0, b1); }
        g_bfrag[t * 2]     = r0;
        g_bfrag[t * 2 + 1] = r1;
    } else if (t < 16384 + 1024) {       // W_enc fragment
        int e = t - 16384;
        int lane = e & 31, term = (e >> 5) & 1, nt = (e >> 6) & 3, kt = e >> 8;
        int n = nt * 8 + (lane >> 2);
        int k = kt * 16 + 2 * (lane & 3);
        float a0 = W_enc[k * DZ + n],       a1 = W_enc[(k + 1) * DZ + n];
        float b0 = W_enc[(k + 8) * DZ + n], b1 = W_enc[(k + 9) * DZ + n];
        uint2 v;
        if (term == 0) { v.x = pack_bf2(a0, a1); v.y = pack_bf2(b0, b1); }
        else           { v.x = pack_lo2(a0, a1); v.y = pack_lo2(b0, b1); }
        g_wef[e] = v;
    } else if (t < 16384 + 2048) {       // W_dec fragment
        int e = t - 16384 - 1024;
        int lane = e & 31, term = (e >> 5) & 1, nt = (e >> 6) & 7, kt = e >> 9;
        int n = nt * 8 + (lane >> 2);
        int k = kt * 16 + 2 * (lane & 3);
        float a0 = W_dec[k * DX + n],       a1 = W_dec[(k + 1) * DX + n];
        float b0 = W_dec[(k + 8) * DX + n], b1 = W_dec[(k + 9) * DX + n];
        uint2 v;
        if (term == 0) { v.x = pack_bf2(a0, a1); v.y = pack_bf2(b0, b1); }
        else           { v.x = pack_lo2(a0, a1); v.y = pack_lo2(b0, b1); }
        g_wdf[e] = v;
    }

    g_sum[t] = 0.f;
    if (t < NB) {
        float s = 0.f;
#pragma unroll
        for (int d = 0; d < DZ; ++d) {
            float v = vectors[t * DZ + d];
            s = fmaf(v, v, s);
        }
        g_hn[t] = 0.5f * s;
        g_cnt[t] = 0.f;
    }
    if (t == 0) { g_recon = 0.0; g_commit = 0.0; }
}

// ---------------------------------------------------------------------------
// main fused kernel (all three GEMMs on tensor cores, bf16 3-term split):
// encoder MMA -> scores MMA/argmin (z reg->reg) -> gather -> atomics ->
// decoder MMA -> losses.  256 threads, 3 CTAs/SM.
// ---------------------------------------------------------------------------
// smem float offsets:
#define SM_X    0                      // [128][68]  8704
#define SM_ZF   8704                   // [128][34]  4352 (z, then q overlay)
#define SM_HN   13056                  // 1024
#define SM_BENC 14080                  // 32
#define SM_BDEC 14112                  // 64
#define SM_RIDX 14176                  // 128 (int)
#define SM_RED  14304                  // 16
#define SM_TOTAL_FLOATS 14320
#define SMEM_MAIN (SM_TOTAL_FLOATS * 4)

__global__ void __launch_bounds__(256, 3) k_main(
    const float* __restrict__ x, const float* __restrict__ b_enc,
    const float* __restrict__ vectors, const float* __restrict__ b_dec)
{
    extern __shared__ float sm[];
    float* s_x    = sm + SM_X;
    float* s_zf   = sm + SM_ZF;
    float* s_hn   = sm + SM_HN;
    float* s_benc = sm + SM_BENC;
    float* s_bdec = sm + SM_BDEC;
    int*   s_ridx = (int*)(sm + SM_RIDX);
    float* s_red  = sm + SM_RED;

    const int tid  = threadIdx.x;
    const int wid  = tid >> 5;
    const int lane = tid & 31;
    const int g4   = lane >> 2;
    const int t4   = lane & 3;
    const int row0 = blockIdx.x * TR;
    const int r0   = wid * 16 + g4;   // this thread's MMA rows
    const int r1   = r0 + 8;
    const unsigned FULL = 0xFFFFFFFFu;

    // ---- load x tile (padded rows) + biases + hn ----
    {
        const float4* xs = (const float4*)(x + (size_t)row0 * DX);
        for (int n = tid; n < TR * DX / 4; n += 256) {
            int r = n >> 4, i = n & 15;
            ((float4*)(s_x + r * SXP))[i] = xs[n];
        }
        for (int n = tid; n < NB; n += 256) s_hn[n] = g_hn[n];
        if (tid < DZ) s_benc[tid] = b_enc[tid];
        if (tid < DX) s_bdec[tid] = b_dec[tid];
    }
    __syncthreads();

    // ---- encoder: z = x @ W_enc + b_enc via HMMA (3-term bf16) ----
    u32 XAhi[4][4], XAlo[4][4];
#pragma unroll
    for (int kt = 0; kt < 4; ++kt) {
        int kb = kt * 16 + 2 * t4;
        float2 x00 = *(const float2*)(s_x + r0 * SXP + kb);
        float2 x10 = *(const float2*)(s_x + r1 * SXP + kb);
        float2 x01 = *(const float2*)(s_x + r0 * SXP + kb + 8);
        float2 x11 = *(const float2*)(s_x + r1 * SXP + kb + 8);
        XAhi[kt][0] = pack_bf2(x00.x, x00.y);
        XAhi[kt][1] = pack_bf2(x10.x, x10.y);
        XAhi[kt][2] = pack_bf2(x01.x, x01.y);
        XAhi[kt][3] = pack_bf2(x11.x, x11.y);
        XAlo[kt][0] = pack_lo2(x00.x, x00.y);
        XAlo[kt][1] = pack_lo2(x10.x, x10.y);
        XAlo[kt][2] = pack_lo2(x01.x, x01.y);
        XAlo[kt][3] = pack_lo2(x11.x, x11.y);
    }

    float zr[4][4];   // [nt][d] : d0=(r0,c0) d1=(r0,c0+1) d2=(r1,c0) d3=(r1,c0+1)
#pragma unroll
    for (int nt = 0; nt < 4; ++nt) {
        int c0 = nt * 8 + 2 * t4;
        float2 be = *(const float2*)(s_benc + c0);
        float da[4] = {be.x, be.y, be.x, be.y};
        float db[4] = {0.f, 0.f, 0.f, 0.f};
#pragma unroll
        for (int kt = 0; kt < 4; ++kt) {
            uint2 bh = g_wef[((kt * 4 + nt) * 2 + 0) * 32 + lane];
            uint2 bl = g_wef[((kt * 4 + nt) * 2 + 1) * 32 + lane];
            u32 BH[2] = {bh.x, bh.y};
            u32 BL[2] = {bl.x, bl.y};
            if (kt & 1) {
                MMA_BF16(db, XAhi[kt], BH);
                MMA_BF16(da, XAhi[kt], BL);
                MMA_BF16(db, XAlo[kt], BH);
            } else {
                MMA_BF16(da, XAhi[kt], BH);
                MMA_BF16(db, XAhi[kt], BL);
                MMA_BF16(da, XAlo[kt], BH);
            }
        }
#pragma unroll
        for (int i = 0; i < 4; ++i) zr[nt][i] = da[i] + db[i];
        *(float2*)(s_zf + r0 * SZP + c0) = make_float2(zr[nt][0], zr[nt][1]);
        *(float2*)(s_zf + r1 * SZP + c0) = make_float2(zr[nt][2], zr[nt][3]);
    }

    // ---- scores A fragments straight from encoder registers ----
    // kt_s=0 uses nt=0,1 ; kt_s=1 uses nt=2,3
    u32 Ahi[2][4], Alo[2][4];
#pragma unroll
    for (int kt = 0; kt < 2; ++kt) {
        int n0 = kt * 2, n1 = kt * 2 + 1;
        Ahi[kt][0] = pack_bf2(zr[n0][0], zr[n0][1]);
        Ahi[kt][1] = pack_bf2(zr[n0][2], zr[n0][3]);
        Ahi[kt][2] = pack_bf2(zr[n1][0], zr[n1][1]);
        Ahi[kt][3] = pack_bf2(zr[n1][2], zr[n1][3]);
        Alo[kt][0] = pack_lo2(zr[n0][0], zr[n0][1]);
        Alo[kt][1] = pack_lo2(zr[n0][2], zr[n0][3]);
        Alo[kt][2] = pack_lo2(zr[n1][0], zr[n1][1]);
        Alo[kt][3] = pack_lo2(zr[n1][2], zr[n1][3]);
    }
    __syncthreads();   // z visible block-wide (gather reads it later)

    // ---- scores: HMMA over 128 col-chunks, -hn folded into accum init ----
    float best0 = -3.4e38f, best1 = -3.4e38f;
    int   bi0 = 0, bi1 = 0;
    const uint2* bsrc = (const uint2*)g_bfrag + lane;

    uint2 n0 = bsrc[0], n1 = bsrc[32], n2 = bsrc[64], n3 = bsrc[96];
    float2 hnv = *(const float2*)(s_hn + 2 * t4);

#pragma unroll 2
    for (int c = 0; c < NCHUNK; ++c) {
        u32 B0[2] = {n0.x, n0.y};
        u32 B1[2] = {n1.x, n1.y};
        u32 B2[2] = {n2.x, n2.y};
        u32 B3[2] = {n3.x, n3.y};
        float2 hn = hnv;
        if (c + 1 < NCHUNK) {
            const uint2* np = bsrc + (c + 1) * 128;
            n0 = np[0]; n1 = np[32]; n2 = np[64]; n3 = np[96];
            hnv = *(const float2*)(s_hn + (c + 1) * 8 + 2 * t4);
        }

        float da[4] = {-hn.x, -hn.y, -hn.x, -hn.y};
        float db[4] = {0.f, 0.f, 0.f, 0.f};
        MMA_BF16(da, Ahi[0], B0);
        MMA_BF16(db, Ahi[1], B1);
        MMA_BF16(da, Ahi[0], B2);
        MMA_BF16(db, Ahi[1], B3);
        MMA_BF16(da, Alo[0], B0);
        MMA_BF16(db, Alo[1], B1);

        int col0 = c * 8 + 2 * t4;
        float s0 = da[0] + db[0];
        float s1 = da[1] + db[1];
        float s2 = da[2] + db[2];
        float s3 = da[3] + db[3];

        bool c0 = s1 > s0;
        float v0 = c0 ? s1 : s0; int i0 = col0 + (int)c0;
        bool c1 = s3 > s2;
        float v1 = c1 ? s3 : s2; int i1 = col0 + (int)c1;
        if (v0 > best0) { best0 = v0; bi0 = i0; }
        if (v1 > best1) { best1 = v1; bi1 = i1; }
    }

    // ---- quad reduce (lanes sharing rows), lowest index on ties ----
#pragma unroll
    for (int off = 1; off <= 2; off <<= 1) {
        float ob0 = __shfl_xor_sync(FULL, best0, off);
        int   oi0 = __shfl_xor_sync(FULL, bi0, off);
        if (ob0 > best0 || (ob0 == best0 && oi0 < bi0)) { best0 = ob0; bi0 = oi0; }
        float ob1 = __shfl_xor_sync(FULL, best1, off);
        int   oi1 = __shfl_xor_sync(FULL, bi1, off);
        if (ob1 > best1 || (ob1 == best1 && oi1 < bi1)) { best1 = ob1; bi1 = oi1; }
    }
    if (t4 == 0) { s_ridx[r0] = bi0; s_ridx[r1] = bi1; }
    __syncthreads();

    // ---- gather q + commitment + segment-sum atomics (z then q overlay) ---
    float commit = 0.f;
    {
        const int col = lane;
        const int rbg = wid * 16;
#pragma unroll
        for (int rr = 0; rr < 16; ++rr) {
            int r = rbg + rr;
            int b = s_ridx[r];
            float zz = s_zf[r * SZP + col];
            float q = vectors[(size_t)b * DZ + col];
            s_zf[r * SZP + col] = q;   // same thread, same address: overlay OK
            float df = q - zz;
            commit = fmaf(df, df, commit);
            atomicAdd(&g_sum[b * DZ + col], zz);
            if (col == 0) atomicAdd(&g_cnt[b], 1.f);
        }
    }
    __syncthreads();  // q complete block-wide

    // ---- decoder: mu = q @ W_dec + b_dec via HMMA; recon partial ----
    u32 QAhi[2][4], QAlo[2][4];
#pragma unroll
    for (int kt = 0; kt < 2; ++kt) {
        int kb = kt * 16 + 2 * t4;
        float2 q00 = *(const float2*)(s_zf + r0 * SZP + kb);
        float2 q10 = *(const float2*)(s_zf + r1 * SZP + kb);
        float2 q01 = *(const float2*)(s_zf + r0 * SZP + kb + 8);
        float2 q11 = *(const float2*)(s_zf + r1 * SZP + kb + 8);
        QAhi[kt][0] = pack_bf2(q00.x, q00.y);
        QAhi[kt][1] = pack_bf2(q10.x, q10.y);
        QAhi[kt][2] = pack_bf2(q01.x, q01.y);
        QAhi[kt][3] = pack_bf2(q11.x, q11.y);
        QAlo[kt][0] = pack_lo2(q00.x, q00.y);
        QAlo[kt][1] = pack_lo2(q10.x, q10.y);
        QAlo[kt][2] = pack_lo2(q01.x, q01.y);
        QAlo[kt][3] = pack_lo2(q11.x, q11.y);
    }

    float recon = 0.f;
#pragma unroll
    for (int nt = 0; nt < 8; ++nt) {
        int c0 = nt * 8 + 2 * t4;
        float2 bd = *(const float2*)(s_bdec + c0);
        float da[4] = {bd.x, bd.y, bd.x, bd.y};
        float db[4] = {0.f, 0.f, 0.f, 0.f};
#pragma unroll
        for (int kt = 0; kt < 2; ++kt) {
            uint2 bh = g_wdf[((kt * 8 + nt) * 2 + 0) * 32 + lane];
            uint2 bl = g_wdf[((kt * 8 + nt) * 2 + 1) * 32 + lane];
            u32 BH[2] = {bh.x, bh.y};
            u32 BL[2] = {bl.x, bl.y};
            if (kt) {
                MMA_BF16(db, QAhi[kt], BH);
                MMA_BF16(da, QAhi[kt], BL);
                MMA_BF16(db, QAlo[kt], BH);
            } else {
                MMA_BF16(da, QAhi[kt], BH);
                MMA_BF16(db, QAhi[kt], BL);
                MMA_BF16(da, QAlo[kt], BH);
            }
        }
        float2 x0 = *(const float2*)(s_x + r0 * SXP + c0);
        float2 x1 = *(const float2*)(s_x + r1 * SXP + c0);
        float d0 = x0.x - (da[0] + db[0]);
        float d1 = x0.y - (da[1] + db[1]);
        float d2 = x1.x - (da[2] + db[2]);
        float d3 = x1.y - (da[3] + db[3]);
        recon = fmaf(d0, d0, recon);
        recon = fmaf(d1, d1, recon);
        recon = fmaf(d2, d2, recon);
        recon = fmaf(d3, d3, recon);
    }

    // ---- block reduce losses -> double atomics ----
#pragma unroll
    for (int off = 16; off; off >>= 1) {
        commit += __shfl_xor_sync(FULL, commit, off);
        recon  += __shfl_xor_sync(FULL, recon, off);
    }
    if (lane == 0) { s_red[wid] = commit; s_red[8 + wid] = recon; }
    __syncthreads();
    if (tid == 0) {
        float cs = 0.f, rs = 0.f;
        for (int w = 0; w < 8; w++) { cs += s_red[w]; rs += s_red[8 + w]; }
        atomicAdd(&g_commit, (double)cs);
        atomicAdd(&g_recon,  (double)rs);
    }
}

// ---------------------------------------------------------------------------
// final1: aem, argmax, dead-code scan (fast path when none dead); loss + aem
// ---------------------------------------------------------------------------
__global__ void k_final1(const float* __restrict__ assignments,
                         float* __restrict__ out)
{
    __shared__ float s_aem[NB];
    __shared__ unsigned char s_na[NB];
    __shared__ unsigned char s_code[NB];
    __shared__ float s_rmax[32];
    __shared__ int   s_rmaxi[32];
    __shared__ int   s_maxidx;
    const unsigned FULL = 0xFFFFFFFFu;
    int tid = threadIdx.x;  // 1024 threads, tid == bin

    float c = g_cnt[tid];
    float ba = c * (1.0f / (float)NROWS);
    float aem = 0.99f * assignments[tid] + 0.01f * ba;
    s_aem[tid] = aem;
    int na = (aem * (float)NROWS) < 9.765625e-05f ? 1 : 0;
    s_na[tid] = (unsigned char)na;
    s_code[tid] = 0;

    float mv = c; int mi = tid;
#pragma unroll
    for (int off = 16; off; off >>= 1) {
        float ov = __shfl_xor_sync(FULL, mv, off);
        int   oi = __shfl_xor_sync(FULL, mi, off);
        if (ov > mv || (ov == mv && oi < mi)) { mv = ov; mi = oi; }
    }
    if ((tid & 31) == 0) { s_rmax[tid >> 5] = mv; s_rmaxi[tid >> 5] = mi; }
    int any_na = __syncthreads_or(na);
    if (tid == 0) {
        float m = s_rmax[0]; int midx = s_rmaxi[0];
        for (int w = 1; w < 32; w++) {
            if (s_rmax[w] > m || (s_rmax[w] == m && s_rmaxi[w] < midx)) {
                m = s_rmax[w]; midx = s_rmaxi[w];
            }
        }
        s_maxidx = midx;
        g_midx = midx;
    }
    __syncthreads();

    if (any_na) {
        if (tid == 0) {
            int midx = s_maxidx;
            bool maxRe = false;
            for (int i = NB - 1; i >= 0; --i) {
                if (s_na[i]) {
                    float na2 = s_aem[midx] * 0.5f;
                    s_code[i] = maxRe ? 2 : 1;
                    s_aem[i] = na2;
                    s_aem[midx] = na2;
                    if (i == midx) maxRe = true;
                }
            }
        }
        __syncthreads();
    }

    g_code[tid] = s_code[tid];
    out[1 + NB * DZ + tid] = s_aem[tid];

    if (tid == 0) {
        double recon = 0.5 * (g_recon / (double)NROWS)
                     + 32.0 * 1.8378770664093453;   // 0.5*d_x*log(2*pi)
        double commit = g_commit / ((double)NROWS * (double)DZ);
        out[0] = (float)(recon + 0.25 * commit);
    }
}

// ---------------------------------------------------------------------------
// final2: new_vectors (parallel, 32 blocks x 1024)
// ---------------------------------------------------------------------------
__global__ void k_final2(const float* __restrict__ vectors,
                         const float* __restrict__ noise,
                         float* __restrict__ out)
{
    int n = blockIdx.x * 1024 + threadIdx.x;  // 0..32767
    int b = n >> 5, d = n & 31;
    int midx = g_midx;
    float sz = g_sum[n];
    unsigned char code = g_code[b];
    float v2;
    if (code == 0) {
        v2 = vectors[n];
    } else {
        v2 = vectors[midx * DZ + d] + noise[n];
        if (code == 2) v2 += noise[midx * DZ + d];
    }
    float cntb = g_cnt[b];
    float mean = (cntb > 0.f) ? (sz / cntb) : v2;
    out[1 + n] = 0.99f * v2 + 0.01f * mean;
}

// ---------------------------------------------------------------------------
extern "C" void kernel_launch(void* const* d_in, const int* in_sizes, int n_in,
                              void* d_out, int out_size) {
    const float* x           = (const float*)d_in[0];
    const float* W_enc       = (const float*)d_in[1];
    const float* b_enc       = (const float*)d_in[2];
    const float* vectors     = (const float*)d_in[3];
    const float* W_dec       = (const float*)d_in[4];
    const float* b_dec       = (const float*)d_in[5];
    const float* assignments = (const float*)d_in[6];
    const float* noise       = (const float*)d_in[7];
    float* out = (float*)d_out;

    cudaFuncSetAttribute(k_main, cudaFuncAttributeMaxDynamicSharedMemorySize,
                         SMEM_MAIN);

    k_init<<<128, 256>>>(vectors, W_enc, W_dec);
    k_main<<<GRID_MAIN, 256, SMEM_MAIN>>>(x, b_enc, vectors, b_dec);
    k_final1<<<1, 1024>>>(assignments, out);
    k_final2<<<32, 1024>>>(vectors, noise, out);
}

// round 8
// speedup vs baseline: 4.6446x; 1.0113x over previous
#include <cuda_runtime.h>
#include <cuda_bf16.h>
#include <math.h>
#include <stdint.h>

typedef unsigned long long u64;
typedef unsigned int u32;

// Problem constants
#define NROWS 262144
#define DX 64
#define DZ 32
#define NB 1024
#define TR 256
#define GRID_MAIN (NROWS / TR)   // 1024
#define NCHUNK 128               // 1024 cols / 8
#define SZP 34                   // s_zf row stride (floats)

// Scratch globals
// Codebook B fragments (HMMA m16n8k16 layout):
// [chunk 128][tile 4][lane 32][reg 2]; tile: 0=v_hi k0-15, 1=v_hi k16-31,
//                                            2=v_lo k0-15, 3=v_lo k16-31
__device__ u32    g_bfrag[NCHUNK * 4 * 32 * 2];   // 131 KB
// W_enc fragments: [(kt*4+nt)*2+term][lane] ; term 0=hi 1=lo
__device__ uint2  g_wef[4 * 4 * 2 * 32];
// W_dec fragments: [(kt*8+nt)*2+term][lane]
__device__ uint2  g_wdf[2 * 8 * 2 * 32];
__device__ float  g_hn[NB];            // 0.5*||v||^2 (fp32 exact)
__device__ float  g_sum[NB * DZ];      // global sum_z accumulator
__device__ float  g_cnt[NB];           // global count accumulator
__device__ unsigned char g_code[NB];
__device__ int    g_midx;
__device__ double g_recon;
__device__ double g_commit;

__device__ __forceinline__ u32 pack_bf2(float f0, float f1) {
    __nv_bfloat162 h = __floats2bfloat162_rn(f0, f1);
    return *(u32*)&h;
}
__device__ __forceinline__ float bf_hi(float f) {
    return __bfloat162float(__float2bfloat16(f));
}
__device__ __forceinline__ u32 pack_lo2(float f0, float f1) {
    return pack_bf2(f0 - bf_hi(f0), f1 - bf_hi(f1));
}
// B-fragment load, L1-sticky
__device__ __forceinline__ uint2 ldg_b(const uint2* p) {
    uint2 v;
    asm volatile("ld.global.nc.L1::evict_last.v2.u32 {%0,%1}, [%2];"
                 : "=r"(v.x), "=r"(v.y) : "l"(p));
    return v;
}

#define MMA_BF16(d, a, b) \
    asm volatile( \
        "mma.sync.aligned.m16n8k16.row.col.f32.bf16.bf16.f32 " \
        "{%0,%1,%2,%3},{%4,%5,%6,%7},{%8,%9},{%0,%1,%2,%3};" \
        : "+f"(d[0]), "+f"(d[1]), "+f"(d[2]), "+f"(d[3]) \
        : "r"(a[0]), "r"(a[1]), "r"(a[2]), "r"(a[3]), "r"(b[0]), "r"(b[1]))

// ---------------------------------------------------------------------------
// init: codebook/W fragments (hi/lo), hn, zero accumulators. 32768 threads.
// ---------------------------------------------------------------------------
__global__ void k_init(const float* __restrict__ vectors,
                       const float* __restrict__ W_enc,
                       const float* __restrict__ W_dec) {
    int t = blockIdx.x * blockDim.x + threadIdx.x;  // 0..32767

    if (t < NCHUNK * 4 * 32) {           // codebook fragment slot
        int lane  = t & 31;
        int tile  = (t >> 5) & 3;
        int chunk = t >> 7;
        int n  = chunk * 8 + (lane >> 2);
        int tt = lane & 3;
        int kbase = (tile & 1) * 16 + 2 * tt;
        const float* vr = vectors + (size_t)n * DZ;
        float a0 = vr[kbase],     a1 = vr[kbase + 1];
        float b0 = vr[kbase + 8], b1 = vr[kbase + 9];
        u32 r0, r1;
        if (tile < 2) { r0 = pack_bf2(a0, a1); r1 = pack_bf2(b0, b1); }
        else          { r0 = pack_lo2(a0, a1); r1 = pack_lo2(b0, b1); }
        g_bfrag[t * 2]     = r0;
        g_bfrag[t * 2 + 1] = r1;
    } else if (t < 16384 + 1024) {       // W_enc fragment
        int e = t - 16384;
        int lane = e & 31, term = (e >> 5) & 1, nt = (e >> 6) & 3, kt = e >> 8;
        int n = nt * 8 + (lane >> 2);
        int k = kt * 16 + 2 * (lane & 3);
        float a0 = W_enc[k * DZ + n],       a1 = W_enc[(k + 1) * DZ + n];
        float b0 = W_enc[(k + 8) * DZ + n], b1 = W_enc[(k + 9) * DZ + n];
        uint2 v;
        if (term == 0) { v.x = pack_bf2(a0, a1); v.y = pack_bf2(b0, b1); }
        else           { v.x = pack_lo2(a0, a1); v.y = pack_lo2(b0, b1); }
        g_wef[e] = v;
    } else if (t < 16384 + 2048) {       // W_dec fragment
        int e = t - 16384 - 1024;
        int lane = e & 31, term = (e >> 5) & 1, nt = (e >> 6) & 7, kt = e >> 9;
        int n = nt * 8 + (lane >> 2);
        int k = kt * 16 + 2 * (lane & 3);
        float a0 = W_dec[k * DX + n],       a1 = W_dec[(k + 1) * DX + n];
        float b0 = W_dec[(k + 8) * DX + n], b1 = W_dec[(k + 9) * DX + n];
        uint2 v;
        if (term == 0) { v.x = pack_bf2(a0, a1); v.y = pack_bf2(b0, b1); }
        else           { v.x = pack_lo2(a0, a1); v.y = pack_lo2(b0, b1); }
        g_wdf[e] = v;
    }

    g_sum[t] = 0.f;
    if (t < NB) {
        float s = 0.f;
#pragma unroll
        for (int d = 0; d < DZ; ++d) {
            float v = vectors[t * DZ + d];
            s = fmaf(v, v, s);
        }
        g_hn[t] = 0.5f * s;
        g_cnt[t] = 0.f;
    }
    if (t == 0) { g_recon = 0.0; g_commit = 0.0; }
}

// ---------------------------------------------------------------------------
// main fused kernel: 256 rows/CTA, each warp 32 rows (two m16 tiles).
// encoder MMA (x from gmem) -> scores MMA/argmin (B reused across 2 tiles,
// L1-resident) -> gather/atomics -> decoder MMA -> losses.
// 256 threads, 2 CTAs/SM (smem ~40 KB -> B fits L1 carveout).
// ---------------------------------------------------------------------------
// smem float offsets:
#define SM_ZF   0                      // [256][34] 8704 (z, then q overlay)
#define SM_HN   8704                   // 1024
#define SM_BENC 9728                   // 32
#define SM_BDEC 9760                   // 64
#define SM_RIDX 9824                   // 256 (int)
#define SM_RED  10080                  // 16
#define SM_TOTAL_FLOATS 10096
#define SMEM_MAIN (SM_TOTAL_FLOATS * 4)

__global__ void __launch_bounds__(256, 2) k_main(
    const float* __restrict__ x, const float* __restrict__ b_enc,
    const float* __restrict__ vectors, const float* __restrict__ b_dec)
{
    extern __shared__ float sm[];
    float* s_zf   = sm + SM_ZF;
    float* s_hn   = sm + SM_HN;
    float* s_benc = sm + SM_BENC;
    float* s_bdec = sm + SM_BDEC;
    int*   s_ridx = (int*)(sm + SM_RIDX);
    float* s_red  = sm + SM_RED;

    const int tid  = threadIdx.x;
    const int wid  = tid >> 5;
    const int lane = tid & 31;
    const int g4   = lane >> 2;
    const int t4   = lane & 3;
    const int row0 = blockIdx.x * TR;
    const unsigned FULL = 0xFFFFFFFFu;

    // ---- biases + hn into smem ----
    for (int n = tid; n < NB; n += 256) s_hn[n] = g_hn[n];
    if (tid < DZ) s_benc[tid] = b_enc[tid];
    if (tid < DX) s_bdec[tid] = b_dec[tid];
    __syncthreads();

    // ---- encoder (per tile): z = x @ W_enc + b_enc via HMMA; A-frags for
    //      the scores GEMM are built straight from the encoder registers ----
    u32 Ahi[2][2][4], Alo[2][2][4];   // [tile][kt][frag]
#pragma unroll
    for (int tile = 0; tile < 2; ++tile) {
        const int r0 = wid * 32 + tile * 16 + g4;
        const int r1 = r0 + 8;
        const float2* px0 = (const float2*)(x + (size_t)(row0 + r0) * DX);
        const float2* px1 = (const float2*)(x + (size_t)(row0 + r1) * DX);

        u32 XAhi[4][4], XAlo[4][4];
#pragma unroll
        for (int kt = 0; kt < 4; ++kt) {
            int i0 = kt * 8 + t4;          // float2 index of col kt*16+2t4
            float2 x00 = px0[i0],     x10 = px1[i0];
            float2 x01 = px0[i0 + 4], x11 = px1[i0 + 4];
            XAhi[kt][0] = pack_bf2(x00.x, x00.y);
            XAhi[kt][1] = pack_bf2(x10.x, x10.y);
            XAhi[kt][2] = pack_bf2(x01.x, x01.y);
            XAhi[kt][3] = pack_bf2(x11.x, x11.y);
            XAlo[kt][0] = pack_lo2(x00.x, x00.y);
            XAlo[kt][1] = pack_lo2(x10.x, x10.y);
            XAlo[kt][2] = pack_lo2(x01.x, x01.y);
            XAlo[kt][3] = pack_lo2(x11.x, x11.y);
        }

        float zr[4][4];
#pragma unroll
        for (int nt = 0; nt < 4; ++nt) {
            int c0 = nt * 8 + 2 * t4;
            float2 be = *(const float2*)(s_benc + c0);
            float da[4] = {be.x, be.y, be.x, be.y};
            float db[4] = {0.f, 0.f, 0.f, 0.f};
#pragma unroll
            for (int kt = 0; kt < 4; ++kt) {
                uint2 bh = g_wef[((kt * 4 + nt) * 2 + 0) * 32 + lane];
                uint2 bl = g_wef[((kt * 4 + nt) * 2 + 1) * 32 + lane];
                u32 BH[2] = {bh.x, bh.y};
                u32 BL[2] = {bl.x, bl.y};
                if (kt & 1) {
                    MMA_BF16(db, XAhi[kt], BH);
                    MMA_BF16(da, XAhi[kt], BL);
                    MMA_BF16(db, XAlo[kt], BH);
                } else {
                    MMA_BF16(da, XAhi[kt], BH);
                    MMA_BF16(db, XAhi[kt], BL);
                    MMA_BF16(da, XAlo[kt], BH);
                }
            }
#pragma unroll
            for (int i = 0; i < 4; ++i) zr[nt][i] = da[i] + db[i];
            *(float2*)(s_zf + r0 * SZP + c0) = make_float2(zr[nt][0], zr[nt][1]);
            *(float2*)(s_zf + r1 * SZP + c0) = make_float2(zr[nt][2], zr[nt][3]);
        }

        // scores A fragments: kt_s=0 <- nt0,1 ; kt_s=1 <- nt2,3
#pragma unroll
        for (int kt = 0; kt < 2; ++kt) {
            int n0 = kt * 2, n1 = kt * 2 + 1;
            Ahi[tile][kt][0] = pack_bf2(zr[n0][0], zr[n0][1]);
            Ahi[tile][kt][1] = pack_bf2(zr[n0][2], zr[n0][3]);
            Ahi[tile][kt][2] = pack_bf2(zr[n1][0], zr[n1][1]);
            Ahi[tile][kt][3] = pack_bf2(zr[n1][2], zr[n1][3]);
            Alo[tile][kt][0] = pack_lo2(zr[n0][0], zr[n0][1]);
            Alo[tile][kt][1] = pack_lo2(zr[n0][2], zr[n0][3]);
            Alo[tile][kt][2] = pack_lo2(zr[n1][0], zr[n1][1]);
            Alo[tile][kt][3] = pack_lo2(zr[n1][2], zr[n1][3]);
        }
    }
    __syncthreads();   // z visible block-wide (gather reads it later)

    // ---- scores: 12 HMMA per chunk (B reused across both tiles) ----
    float best[4] = {-3.4e38f, -3.4e38f, -3.4e38f, -3.4e38f};
    int   bidx[4] = {0, 0, 0, 0};
    const uint2* bsrc = (const uint2*)g_bfrag + lane;

    uint2 n0 = ldg_b(bsrc), n1 = ldg_b(bsrc + 32),
          n2 = ldg_b(bsrc + 64), n3 = ldg_b(bsrc + 96);
    float2 hnv = *(const float2*)(s_hn + 2 * t4);

#pragma unroll 2
    for (int c = 0; c < NCHUNK; ++c) {
        u32 B0[2] = {n0.x, n0.y};
        u32 B1[2] = {n1.x, n1.y};
        u32 B2[2] = {n2.x, n2.y};
        u32 B3[2] = {n3.x, n3.y};
        float2 hn = hnv;
        if (c + 1 < NCHUNK) {
            const uint2* np = bsrc + (c + 1) * 128;
            n0 = ldg_b(np); n1 = ldg_b(np + 32);
            n2 = ldg_b(np + 64); n3 = ldg_b(np + 96);
            hnv = *(const float2*)(s_hn + (c + 1) * 8 + 2 * t4);
        }

        float da0[4] = {-hn.x, -hn.y, -hn.x, -hn.y};
        float db0[4] = {0.f, 0.f, 0.f, 0.f};
        float da1[4] = {-hn.x, -hn.y, -hn.x, -hn.y};
        float db1[4] = {0.f, 0.f, 0.f, 0.f};
        MMA_BF16(da0, Ahi[0][0], B0);
        MMA_BF16(db0, Ahi[0][1], B1);
        MMA_BF16(da1, Ahi[1][0], B0);
        MMA_BF16(db1, Ahi[1][1], B1);
        MMA_BF16(da0, Ahi[0][0], B2);
        MMA_BF16(db0, Ahi[0][1], B3);
        MMA_BF16(da1, Ahi[1][0], B2);
        MMA_BF16(db1, Ahi[1][1], B3);
        MMA_BF16(da0, Alo[0][0], B0);
        MMA_BF16(db0, Alo[0][1], B1);
        MMA_BF16(da1, Alo[1][0], B0);
        MMA_BF16(db1, Alo[1][1], B1);

        int col0 = c * 8 + 2 * t4;
#pragma unroll
        for (int tile = 0; tile < 2; ++tile) {
            const float* da = tile ? da1 : da0;
            const float* db = tile ? db1 : db0;
            float s0 = da[0] + db[0];
            float s1 = da[1] + db[1];
            float s2 = da[2] + db[2];
            float s3 = da[3] + db[3];
            bool c0 = s1 > s0;
            float v0 = c0 ? s1 : s0; int i0 = col0 + (int)c0;
            bool c1 = s3 > s2;
            float v1 = c1 ? s3 : s2; int i1 = col0 + (int)c1;
            if (v0 > best[tile * 2])     { best[tile * 2] = v0;     bidx[tile * 2] = i0; }
            if (v1 > best[tile * 2 + 1]) { best[tile * 2 + 1] = v1; bidx[tile * 2 + 1] = i1; }
        }
    }

    // ---- quad reduce (lanes sharing rows), lowest index on ties ----
#pragma unroll
    for (int i = 0; i < 4; ++i) {
        float bs = best[i]; int bi = bidx[i];
#pragma unroll
        for (int off = 1; off <= 2; off <<= 1) {
            float ob = __shfl_xor_sync(FULL, bs, off);
            int   oi = __shfl_xor_sync(FULL, bi, off);
            if (ob > bs || (ob == bs && oi < bi)) { bs = ob; bi = oi; }
        }
        if (t4 == 0) {
            int tile = i >> 1, half = i & 1;
            s_ridx[wid * 32 + tile * 16 + half * 8 + g4] = bi;
        }
    }
    __syncthreads();

    // ---- gather q + commitment + segment-sum atomics (z then q overlay) ---
    float commit = 0.f;
    {
        const int col = lane;
        const int rbg = wid * 32;
#pragma unroll
        for (int rr = 0; rr < 32; ++rr) {
            int r = rbg + rr;
            int b = s_ridx[r];
            float zz = s_zf[r * SZP + col];
            float q = vectors[(size_t)b * DZ + col];
            s_zf[r * SZP + col] = q;   // same thread, same address: overlay OK
            float df = q - zz;
            commit = fmaf(df, df, commit);
            atomicAdd(&g_sum[b * DZ + col], zz);
            if (col == 0) atomicAdd(&g_cnt[b], 1.f);
        }
    }
    __syncthreads();  // q complete block-wide

    // ---- decoder (per tile): mu = q @ W_dec + b_dec via HMMA; recon ----
    float recon = 0.f;
#pragma unroll
    for (int tile = 0; tile < 2; ++tile) {
        const int r0 = wid * 32 + tile * 16 + g4;
        const int r1 = r0 + 8;
        const float2* px0 = (const float2*)(x + (size_t)(row0 + r0) * DX);
        const float2* px1 = (const float2*)(x + (size_t)(row0 + r1) * DX);

        u32 QAhi[2][4], QAlo[2][4];
#pragma unroll
        for (int kt = 0; kt < 2; ++kt) {
            int kb = kt * 16 + 2 * t4;
            float2 q00 = *(const float2*)(s_zf + r0 * SZP + kb);
            float2 q10 = *(const float2*)(s_zf + r1 * SZP + kb);
            float2 q01 = *(const float2*)(s_zf + r0 * SZP + kb + 8);
            float2 q11 = *(const float2*)(s_zf + r1 * SZP + kb + 8);
            QAhi[kt][0] = pack_bf2(q00.x, q00.y);
            QAhi[kt][1] = pack_bf2(q10.x, q10.y);
            QAhi[kt][2] = pack_bf2(q01.x, q01.y);
            QAhi[kt][3] = pack_bf2(q11.x, q11.y);
            QAlo[kt][0] = pack_lo2(q00.x, q00.y);
            QAlo[kt][1] = pack_lo2(q10.x, q10.y);
            QAlo[kt][2] = pack_lo2(q01.x, q01.y);
            QAlo[kt][3] = pack_lo2(q11.x, q11.y);
        }

#pragma unroll
        for (int nt = 0; nt < 8; ++nt) {
            int c0 = nt * 8 + 2 * t4;
            float2 bd = *(const float2*)(s_bdec + c0);
            float da[4] = {bd.x, bd.y, bd.x, bd.y};
            float db[4] = {0.f, 0.f, 0.f, 0.f};
#pragma unroll
            for (int kt = 0; kt < 2; ++kt) {
                uint2 bh = g_wdf[((kt * 8 + nt) * 2 + 0) * 32 + lane];
                uint2 bl = g_wdf[((kt * 8 + nt) * 2 + 1) * 32 + lane];
                u32 BH[2] = {bh.x, bh.y};
                u32 BL[2] = {bl.x, bl.y};
                if (kt) {
                    MMA_BF16(db, QAhi[kt], BH);
                    MMA_BF16(da, QAhi[kt], BL);
                    MMA_BF16(db, QAlo[kt], BH);
                } else {
                    MMA_BF16(da, QAhi[kt], BH);
                    MMA_BF16(db, QAhi[kt], BL);
                    MMA_BF16(da, QAlo[kt], BH);
                }
            }
            int i0 = nt * 4 + t4;
            float2 x0 = px0[i0];
            float2 x1 = px1[i0];
            float d0 = x0.x - (da[0] + db[0]);
            float d1 = x0.y - (da[1] + db[1]);
            float d2 = x1.x - (da[2] + db[2]);
            float d3 = x1.y - (da[3] + db[3]);
            recon = fmaf(d0, d0, recon);
            recon = fmaf(d1, d1, recon);
            recon = fmaf(d2, d2, recon);
            recon = fmaf(d3, d3, recon);
        }
    }

    // ---- block reduce losses -> double atomics ----
#pragma unroll
    for (int off = 16; off; off >>= 1) {
        commit += __shfl_xor_sync(FULL, commit, off);
        recon  += __shfl_xor_sync(FULL, recon, off);
    }
    if (lane == 0) { s_red[wid] = commit; s_red[8 + wid] = recon; }
    __syncthreads();
    if (tid == 0) {
        float cs = 0.f, rs = 0.f;
        for (int w = 0; w < 8; w++) { cs += s_red[w]; rs += s_red[8 + w]; }
        atomicAdd(&g_commit, (double)cs);
        atomicAdd(&g_recon,  (double)rs);
    }
}

// ---------------------------------------------------------------------------
// final1: aem, argmax, dead-code scan (fast path when none dead); loss + aem
// ---------------------------------------------------------------------------
__global__ void k_final1(const float* __restrict__ assignments,
                         float* __restrict__ out)
{
    __shared__ float s_aem[NB];
    __shared__ unsigned char s_na[NB];
    __shared__ unsigned char s_code[NB];
    __shared__ float s_rmax[32];
    __shared__ int   s_rmaxi[32];
    __shared__ int   s_maxidx;
    const unsigned FULL = 0xFFFFFFFFu;
    int tid = threadIdx.x;  // 1024 threads, tid == bin

    float c = g_cnt[tid];
    float ba = c * (1.0f / (float)NROWS);
    float aem = 0.99f * assignments[tid] + 0.01f * ba;
    s_aem[tid] = aem;
    int na = (aem * (float)NROWS) < 9.765625e-05f ? 1 : 0;
    s_na[tid] = (unsigned char)na;
    s_code[tid] = 0;

    float mv = c; int mi = tid;
#pragma unroll
    for (int off = 16; off; off >>= 1) {
        float ov = __shfl_xor_sync(FULL, mv, off);
        int   oi = __shfl_xor_sync(FULL, mi, off);
        if (ov > mv || (ov == mv && oi < mi)) { mv = ov; mi = oi; }
    }
    if ((tid & 31) == 0) { s_rmax[tid >> 5] = mv; s_rmaxi[tid >> 5] = mi; }
    int any_na = __syncthreads_or(na);
    if (tid == 0) {
        float m = s_rmax[0]; int midx = s_rmaxi[0];
        for (int w = 1; w < 32; w++) {
            if (s_rmax[w] > m || (s_rmax[w] == m && s_rmaxi[w] < midx)) {
                m = s_rmax[w]; midx = s_rmaxi[w];
            }
        }
        s_maxidx = midx;
        g_midx = midx;
    }
    __syncthreads();

    if (any_na) {
        if (tid == 0) {
            int midx = s_maxidx;
            bool maxRe = false;
            for (int i = NB - 1; i >= 0; --i) {
                if (s_na[i]) {
                    float na2 = s_aem[midx] * 0.5f;
                    s_code[i] = maxRe ? 2 : 1;
                    s_aem[i] = na2;
                    s_aem[midx] = na2;
                    if (i == midx) maxRe = true;
                }
            }
        }
        __syncthreads();
    }

    g_code[tid] = s_code[tid];
    out[1 + NB * DZ + tid] = s_aem[tid];

    if (tid == 0) {
        double recon = 0.5 * (g_recon / (double)NROWS)
                     + 32.0 * 1.8378770664093453;   // 0.5*d_x*log(2*pi)
        double commit = g_commit / ((double)NROWS * (double)DZ);
        out[0] = (float)(recon + 0.25 * commit);
    }
}

// ---------------------------------------------------------------------------
// final2: new_vectors (parallel, 32 blocks x 1024)
// ---------------------------------------------------------------------------
__global__ void k_final2(const float* __restrict__ vectors,
                         const float* __restrict__ noise,
                         float* __restrict__ out)
{
    int n = blockIdx.x * 1024 + threadIdx.x;  // 0..32767
    int b = n >> 5, d = n & 31;
    int midx = g_midx;
    float sz = g_sum[n];
    unsigned char code = g_code[b];
    float v2;
    if (code == 0) {
        v2 = vectors[n];
    } else {
        v2 = vectors[midx * DZ + d] + noise[n];
        if (code == 2) v2 += noise[midx * DZ + d];
    }
    float cntb = g_cnt[b];
    float mean = (cntb > 0.f) ? (sz / cntb) : v2;
    out[1 + n] = 0.99f * v2 + 0.01f * mean;
}

// ---------------------------------------------------------------------------
extern "C" void kernel_launch(void* const* d_in, const int* in_sizes, int n_in,
                              void* d_out, int out_size) {
    const float* x           = (const float*)d_in[0];
    const float* W_enc       = (const float*)d_in[1];
    const float* b_enc       = (const float*)d_in[2];
    const float* vectors     = (const float*)d_in[3];
    const float* W_dec       = (const float*)d_in[4];
    const float* b_dec       = (const float*)d_in[5];
    const float* assignments = (const float*)d_in[6];
    const float* noise       = (const float*)d_in[7];
    float* out = (float*)d_out;

    cudaFuncSetAttribute(k_main, cudaFuncAttributeMaxDynamicSharedMemorySize,
                         SMEM_MAIN);

    k_init<<<128, 256>>>(vectors, W_enc, W_dec);
    k_main<<<GRID_MAIN, 256, SMEM_MAIN>>>(x, b_enc, vectors, b_dec);
    k_final1<<<1, 1024>>>(assignments, out);
    k_final2<<<32, 1024>>>(vectors, noise, out);
}

// round 9
// speedup vs baseline: 5.6976x; 1.2267x over previous
#include <cuda_runtime.h>
#include <cuda_fp16.h>
#include <math.h>
#include <stdint.h>

typedef unsigned long long u64;
typedef unsigned int u32;

// Problem constants
#define NROWS 262144
#define DX 64
#define DZ 32
#define NB 1024
#define TR 256
#define GRID_MAIN (NROWS / TR)   // 1024
#define NCHUNK 128               // 1024 cols / 8
#define SZP 34                   // s_zf row stride (floats)

// Scratch globals
// Codebook B fragments (fp16-quantized v, HMMA m16n8k16 layout):
// [chunk 128][ktile 2][lane 32][reg 2] u32   (64 KB)
__device__ u32    g_bfrag[NCHUNK * 2 * 32 * 2];
// W_enc fragments fp16: [(kt*4+nt)*2+term][lane] ; term 0=hi 1=lo
__device__ uint2  g_wef[4 * 4 * 2 * 32];
// W_dec fragments fp16: [(kt*8+nt)*2+term][lane]
__device__ uint2  g_wdf[2 * 8 * 2 * 32];
__device__ float  g_hn[NB];            // 0.5*||fp16(v)||^2 (consistent w/ B)
__device__ float  g_sum[NB * DZ];      // global sum_z accumulator
__device__ float  g_cnt[NB];           // global count accumulator
__device__ unsigned char g_code[NB];
__device__ int    g_midx;
__device__ double g_recon;
__device__ double g_commit;

// pack two floats -> fp16x2 u32 (first element in low half)
__device__ __forceinline__ u32 pack_hf2(float f0, float f1) {
    __half2 h = __floats2half2_rn(f0, f1);
    return *(u32*)&h;
}
__device__ __forceinline__ float hf_hi(float f) {
    return __half2float(__float2half_rn(f));
}
__device__ __forceinline__ u32 pack_hlo2(float f0, float f1) {
    return pack_hf2(f0 - hf_hi(f0), f1 - hf_hi(f1));
}
// B-fragment load, L1-sticky
__device__ __forceinline__ uint2 ldg_b(const uint2* p) {
    uint2 v;
    asm volatile("ld.global.nc.L1::evict_last.v2.u32 {%0,%1}, [%2];"
                 : "=r"(v.x), "=r"(v.y) : "l"(p));
    return v;
}

#define MMA_F16(d, a, b) \
    asm volatile( \
        "mma.sync.aligned.m16n8k16.row.col.f32.f16.f16.f32 " \
        "{%0,%1,%2,%3},{%4,%5,%6,%7},{%8,%9},{%0,%1,%2,%3};" \
        : "+f"(d[0]), "+f"(d[1]), "+f"(d[2]), "+f"(d[3]) \
        : "r"(a[0]), "r"(a[1]), "r"(a[2]), "r"(a[3]), "r"(b[0]), "r"(b[1]))

// ---------------------------------------------------------------------------
// init: codebook/W fragments (fp16), hn on quantized codebook, zero accums.
// 32768 threads.
// ---------------------------------------------------------------------------
__global__ void k_init(const float* __restrict__ vectors,
                       const float* __restrict__ W_enc,
                       const float* __restrict__ W_dec) {
    int t = blockIdx.x * blockDim.x + threadIdx.x;  // 0..32767

    if (t < NCHUNK * 2 * 32) {           // codebook fragment (v_hi only)
        int lane  = t & 31;
        int tile  = (t >> 5) & 1;
        int chunk = t >> 6;
        int n  = chunk * 8 + (lane >> 2);
        int tt = lane & 3;
        int kbase = tile * 16 + 2 * tt;
        const float* vr = vectors + (size_t)n * DZ;
        g_bfrag[t * 2]     = pack_hf2(vr[kbase],     vr[kbase + 1]);
        g_bfrag[t * 2 + 1] = pack_hf2(vr[kbase + 8], vr[kbase + 9]);
    } else if (t < 8192 + 1024) {        // W_enc fragment
        int e = t - 8192;
        int lane = e & 31, term = (e >> 5) & 1, nt = (e >> 6) & 3, kt = e >> 8;
        int n = nt * 8 + (lane >> 2);
        int k = kt * 16 + 2 * (lane & 3);
        float a0 = W_enc[k * DZ + n],       a1 = W_enc[(k + 1) * DZ + n];
        float b0 = W_enc[(k + 8) * DZ + n], b1 = W_enc[(k + 9) * DZ + n];
        uint2 v;
        if (term == 0) { v.x = pack_hf2(a0, a1);  v.y = pack_hf2(b0, b1); }
        else           { v.x = pack_hlo2(a0, a1); v.y = pack_hlo2(b0, b1); }
        g_wef[e] = v;
    } else if (t < 8192 + 1024 + 2048) { // W_dec fragment
        int e = t - 8192 - 1024;
        int lane = e & 31, term = (e >> 5) & 1, nt = (e >> 6) & 7, kt = e >> 9;
        int n = nt * 8 + (lane >> 2);
        int k = kt * 16 + 2 * (lane & 3);
        float a0 = W_dec[k * DX + n],       a1 = W_dec[(k + 1) * DX + n];
        float b0 = W_dec[(k + 8) * DX + n], b1 = W_dec[(k + 9) * DX + n];
        uint2 v;
        if (term == 0) { v.x = pack_hf2(a0, a1);  v.y = pack_hf2(b0, b1); }
        else           { v.x = pack_hlo2(a0, a1); v.y = pack_hlo2(b0, b1); }
        g_wdf[e] = v;
    }

    g_sum[t] = 0.f;
    if (t < NB) {
        float s = 0.f;
#pragma unroll
        for (int d = 0; d < DZ; ++d) {
            float v = hf_hi(vectors[t * DZ + d]);   // quantized, matches B
            s = fmaf(v, v, s);
        }
        g_hn[t] = 0.5f * s;
        g_cnt[t] = 0.f;
    }
    if (t == 0) { g_recon = 0.0; g_commit = 0.0; }
}

// ---------------------------------------------------------------------------
// main fused kernel: 256 rows/CTA, each warp 32 rows (two m16 tiles).
// fp16 encoder MMA -> fp16 scores MMA (z 2-term, v 1-term, consistent hn)
// -> argmin -> gather/atomics -> fp16 decoder MMA -> losses.
// 256 threads, 2 CTAs/SM.
// ---------------------------------------------------------------------------
// smem float offsets:
#define SM_ZF   0                      // [256][34] 8704 (z, then q overlay)
#define SM_HN   8704                   // 1024
#define SM_BENC 9728                   // 32
#define SM_BDEC 9760                   // 64
#define SM_RIDX 9824                   // 256 (int)
#define SM_RED  10080                  // 16
#define SM_TOTAL_FLOATS 10096
#define SMEM_MAIN (SM_TOTAL_FLOATS * 4)

__global__ void __launch_bounds__(256, 2) k_main(
    const float* __restrict__ x, const float* __restrict__ b_enc,
    const float* __restrict__ vectors, const float* __restrict__ b_dec)
{
    extern __shared__ float sm[];
    float* s_zf   = sm + SM_ZF;
    float* s_hn   = sm + SM_HN;
    float* s_benc = sm + SM_BENC;
    float* s_bdec = sm + SM_BDEC;
    int*   s_ridx = (int*)(sm + SM_RIDX);
    float* s_red  = sm + SM_RED;

    const int tid  = threadIdx.x;
    const int wid  = tid >> 5;
    const int lane = tid & 31;
    const int g4   = lane >> 2;
    const int t4   = lane & 3;
    const int row0 = blockIdx.x * TR;
    const unsigned FULL = 0xFFFFFFFFu;

    // ---- biases + hn into smem ----
    for (int n = tid; n < NB; n += 256) s_hn[n] = g_hn[n];
    if (tid < DZ) s_benc[tid] = b_enc[tid];
    if (tid < DX) s_bdec[tid] = b_dec[tid];
    __syncthreads();

    // ---- encoder (per tile): z = x @ W_enc + b_enc via fp16 HMMA; scores
    //      A-fragments (z_hi / z_lo fp16) built straight from registers ----
    u32 Ahi[2][2][4], Alo[2][2][4];   // [tile][kt][frag]
#pragma unroll
    for (int tile = 0; tile < 2; ++tile) {
        const int r0 = wid * 32 + tile * 16 + g4;
        const int r1 = r0 + 8;
        const float2* px0 = (const float2*)(x + (size_t)(row0 + r0) * DX);
        const float2* px1 = (const float2*)(x + (size_t)(row0 + r1) * DX);

        u32 XAhi[4][4], XAlo[4][4];
#pragma unroll
        for (int kt = 0; kt < 4; ++kt) {
            int i0 = kt * 8 + t4;
            float2 x00 = px0[i0],     x10 = px1[i0];
            float2 x01 = px0[i0 + 4], x11 = px1[i0 + 4];
            XAhi[kt][0] = pack_hf2(x00.x, x00.y);
            XAhi[kt][1] = pack_hf2(x10.x, x10.y);
            XAhi[kt][2] = pack_hf2(x01.x, x01.y);
            XAhi[kt][3] = pack_hf2(x11.x, x11.y);
            XAlo[kt][0] = pack_hlo2(x00.x, x00.y);
            XAlo[kt][1] = pack_hlo2(x10.x, x10.y);
            XAlo[kt][2] = pack_hlo2(x01.x, x01.y);
            XAlo[kt][3] = pack_hlo2(x11.x, x11.y);
        }

        float zr[4][4];
#pragma unroll
        for (int nt = 0; nt < 4; ++nt) {
            int c0 = nt * 8 + 2 * t4;
            float2 be = *(const float2*)(s_benc + c0);
            float da[4] = {be.x, be.y, be.x, be.y};
            float db[4] = {0.f, 0.f, 0.f, 0.f};
#pragma unroll
            for (int kt = 0; kt < 4; ++kt) {
                uint2 bh = g_wef[((kt * 4 + nt) * 2 + 0) * 32 + lane];
                uint2 bl = g_wef[((kt * 4 + nt) * 2 + 1) * 32 + lane];
                u32 BH[2] = {bh.x, bh.y};
                u32 BL[2] = {bl.x, bl.y};
                if (kt & 1) {
                    MMA_F16(db, XAhi[kt], BH);
                    MMA_F16(da, XAhi[kt], BL);
                    MMA_F16(db, XAlo[kt], BH);
                } else {
                    MMA_F16(da, XAhi[kt], BH);
                    MMA_F16(db, XAhi[kt], BL);
                    MMA_F16(da, XAlo[kt], BH);
                }
            }
#pragma unroll
            for (int i = 0; i < 4; ++i) zr[nt][i] = da[i] + db[i];
            *(float2*)(s_zf + r0 * SZP + c0) = make_float2(zr[nt][0], zr[nt][1]);
            *(float2*)(s_zf + r1 * SZP + c0) = make_float2(zr[nt][2], zr[nt][3]);
        }

        // scores A fragments (fp16 hi/lo of z): kt=0 <- nt0,1 ; kt=1 <- nt2,3
#pragma unroll
        for (int kt = 0; kt < 2; ++kt) {
            int n0 = kt * 2, n1 = kt * 2 + 1;
            Ahi[tile][kt][0] = pack_hf2(zr[n0][0], zr[n0][1]);
            Ahi[tile][kt][1] = pack_hf2(zr[n0][2], zr[n0][3]);
            Ahi[tile][kt][2] = pack_hf2(zr[n1][0], zr[n1][1]);
            Ahi[tile][kt][3] = pack_hf2(zr[n1][2], zr[n1][3]);
            Alo[tile][kt][0] = pack_hlo2(zr[n0][0], zr[n0][1]);
            Alo[tile][kt][1] = pack_hlo2(zr[n0][2], zr[n0][3]);
            Alo[tile][kt][2] = pack_hlo2(zr[n1][0], zr[n1][1]);
            Alo[tile][kt][3] = pack_hlo2(zr[n1][2], zr[n1][3]);
        }
    }
    __syncthreads();   // z visible block-wide (gather reads it later)

    // ---- scores: 8 HMMA per chunk (v 1-term, z 2-term, B reused) ----
    float best[4] = {-3.4e38f, -3.4e38f, -3.4e38f, -3.4e38f};
    int   bidx[4] = {0, 0, 0, 0};
    const uint2* bsrc = (const uint2*)g_bfrag + lane;

    uint2 n0 = ldg_b(bsrc), n1 = ldg_b(bsrc + 32);
    float2 hnv = *(const float2*)(s_hn + 2 * t4);

#pragma unroll 2
    for (int c = 0; c < NCHUNK; ++c) {
        u32 B0[2] = {n0.x, n0.y};
        u32 B1[2] = {n1.x, n1.y};
        float2 hn = hnv;
        if (c + 1 < NCHUNK) {
            const uint2* np = bsrc + (c + 1) * 64;
            n0 = ldg_b(np); n1 = ldg_b(np + 32);
            hnv = *(const float2*)(s_hn + (c + 1) * 8 + 2 * t4);
        }

        float da0[4] = {-hn.x, -hn.y, -hn.x, -hn.y};
        float db0[4] = {0.f, 0.f, 0.f, 0.f};
        float da1[4] = {-hn.x, -hn.y, -hn.x, -hn.y};
        float db1[4] = {0.f, 0.f, 0.f, 0.f};
        MMA_F16(da0, Ahi[0][0], B0);
        MMA_F16(db0, Ahi[0][1], B1);
        MMA_F16(da1, Ahi[1][0], B0);
        MMA_F16(db1, Ahi[1][1], B1);
        MMA_F16(da0, Alo[0][0], B0);
        MMA_F16(db0, Alo[0][1], B1);
        MMA_F16(da1, Alo[1][0], B0);
        MMA_F16(db1, Alo[1][1], B1);

        int col0 = c * 8 + 2 * t4;
#pragma unroll
        for (int tile = 0; tile < 2; ++tile) {
            const float* da = tile ? da1 : da0;
            const float* db = tile ? db1 : db0;
            float s0 = da[0] + db[0];
            float s1 = da[1] + db[1];
            float s2 = da[2] + db[2];
            float s3 = da[3] + db[3];
            bool c0 = s1 > s0;
            float v0 = c0 ? s1 : s0; int i0 = col0 + (int)c0;
            bool c1 = s3 > s2;
            float v1 = c1 ? s3 : s2; int i1 = col0 + (int)c1;
            if (v0 > best[tile * 2])     { best[tile * 2] = v0;     bidx[tile * 2] = i0; }
            if (v1 > best[tile * 2 + 1]) { best[tile * 2 + 1] = v1; bidx[tile * 2 + 1] = i1; }
        }
    }

    // ---- quad reduce (lanes sharing rows), lowest index on ties ----
#pragma unroll
    for (int i = 0; i < 4; ++i) {
        float bs = best[i]; int bi = bidx[i];
#pragma unroll
        for (int off = 1; off <= 2; off <<= 1) {
            float ob = __shfl_xor_sync(FULL, bs, off);
            int   oi = __shfl_xor_sync(FULL, bi, off);
            if (ob > bs || (ob == bs && oi < bi)) { bs = ob; bi = oi; }
        }
        if (t4 == 0) {
            int tile = i >> 1, half = i & 1;
            s_ridx[wid * 32 + tile * 16 + half * 8 + g4] = bi;
        }
    }
    __syncthreads();

    // ---- gather q + commitment + segment-sum atomics (z then q overlay) ---
    float commit = 0.f;
    {
        const int col = lane;
        const int rbg = wid * 32;
#pragma unroll
        for (int rr = 0; rr < 32; ++rr) {
            int r = rbg + rr;
            int b = s_ridx[r];
            float zz = s_zf[r * SZP + col];
            float q = vectors[(size_t)b * DZ + col];
            s_zf[r * SZP + col] = q;   // same thread, same address: overlay OK
            float df = q - zz;
            commit = fmaf(df, df, commit);
            atomicAdd(&g_sum[b * DZ + col], zz);
            if (col == 0) atomicAdd(&g_cnt[b], 1.f);
        }
    }
    __syncthreads();  // q complete block-wide

    // ---- decoder (per tile): mu = q @ W_dec + b_dec via fp16 HMMA; recon --
    float recon = 0.f;
#pragma unroll
    for (int tile = 0; tile < 2; ++tile) {
        const int r0 = wid * 32 + tile * 16 + g4;
        const int r1 = r0 + 8;
        const float2* px0 = (const float2*)(x + (size_t)(row0 + r0) * DX);
        const float2* px1 = (const float2*)(x + (size_t)(row0 + r1) * DX);

        u32 QAhi[2][4], QAlo[2][4];
#pragma unroll
        for (int kt = 0; kt < 2; ++kt) {
            int kb = kt * 16 + 2 * t4;
            float2 q00 = *(const float2*)(s_zf + r0 * SZP + kb);
            float2 q10 = *(const float2*)(s_zf + r1 * SZP + kb);
            float2 q01 = *(const float2*)(s_zf + r0 * SZP + kb + 8);
            float2 q11 = *(const float2*)(s_zf + r1 * SZP + kb + 8);
            QAhi[kt][0] = pack_hf2(q00.x, q00.y);
            QAhi[kt][1] = pack_hf2(q10.x, q10.y);
            QAhi[kt][2] = pack_hf2(q01.x, q01.y);
            QAhi[kt][3] = pack_hf2(q11.x, q11.y);
            QAlo[kt][0] = pack_hlo2(q00.x, q00.y);
            QAlo[kt][1] = pack_hlo2(q10.x, q10.y);
            QAlo[kt][2] = pack_hlo2(q01.x, q01.y);
            QAlo[kt][3] = pack_hlo2(q11.x, q11.y);
        }

#pragma unroll
        for (int nt = 0; nt < 8; ++nt) {
            int c0 = nt * 8 + 2 * t4;
            float2 bd = *(const float2*)(s_bdec + c0);
            float da[4] = {bd.x, bd.y, bd.x, bd.y};
            float db[4] = {0.f, 0.f, 0.f, 0.f};
#pragma unroll
            for (int kt = 0; kt < 2; ++kt) {
                uint2 bh = g_wdf[((kt * 8 + nt) * 2 + 0) * 32 + lane];
                uint2 bl = g_wdf[((kt * 8 + nt) * 2 + 1) * 32 + lane];
                u32 BH[2] = {bh.x, bh.y};
                u32 BL[2] = {bl.x, bl.y};
                if (kt) {
                    MMA_F16(db, QAhi[kt], BH);
                    MMA_F16(da, QAhi[kt], BL);
                    MMA_F16(db, QAlo[kt], BH);
                } else {
                    MMA_F16(da, QAhi[kt], BH);
                    MMA_F16(db, QAhi[kt], BL);
                    MMA_F16(da, QAlo[kt], BH);
                }
            }
            int i0 = nt * 4 + t4;
            float2 x0 = px0[i0];
            float2 x1 = px1[i0];
            float d0 = x0.x - (da[0] + db[0]);
            float d1 = x0.y - (da[1] + db[1]);
            float d2 = x1.x - (da[2] + db[2]);
            float d3 = x1.y - (da[3] + db[3]);
            recon = fmaf(d0, d0, recon);
            recon = fmaf(d1, d1, recon);
            recon = fmaf(d2, d2, recon);
            recon = fmaf(d3, d3, recon);
        }
    }

    // ---- block reduce losses -> double atomics ----
#pragma unroll
    for (int off = 16; off; off >>= 1) {
        commit += __shfl_xor_sync(FULL, commit, off);
        recon  += __shfl_xor_sync(FULL, recon, off);
    }
    if (lane == 0) { s_red[wid] = commit; s_red[8 + wid] = recon; }
    __syncthreads();
    if (tid == 0) {
        float cs = 0.f, rs = 0.f;
        for (int w = 0; w < 8; w++) { cs += s_red[w]; rs += s_red[8 + w]; }
        atomicAdd(&g_commit, (double)cs);
        atomicAdd(&g_recon,  (double)rs);
    }
}

// ---------------------------------------------------------------------------
// final1: aem, argmax, dead-code scan (fast path when none dead); loss + aem
// ---------------------------------------------------------------------------
__global__ void k_final1(const float* __restrict__ assignments,
                         float* __restrict__ out)
{
    __shared__ float s_aem[NB];
    __shared__ unsigned char s_na[NB];
    __shared__ unsigned char s_code[NB];
    __shared__ float s_rmax[32];
    __shared__ int   s_rmaxi[32];
    __shared__ int   s_maxidx;
    const unsigned FULL = 0xFFFFFFFFu;
    int tid = threadIdx.x;  // 1024 threads, tid == bin

    float c = g_cnt[tid];
    float ba = c * (1.0f / (float)NROWS);
    float aem = 0.99f * assignments[tid] + 0.01f * ba;
    s_aem[tid] = aem;
    int na = (aem * (float)NROWS) < 9.765625e-05f ? 1 : 0;
    s_na[tid] = (unsigned char)na;
    s_code[tid] = 0;

    float mv = c; int mi = tid;
#pragma unroll
    for (int off = 16; off; off >>= 1) {
        float ov = __shfl_xor_sync(FULL, mv, off);
        int   oi = __shfl_xor_sync(FULL, mi, off);
        if (ov > mv || (ov == mv && oi < mi)) { mv = ov; mi = oi; }
    }
    if ((tid & 31) == 0) { s_rmax[tid >> 5] = mv; s_rmaxi[tid >> 5] = mi; }
    int any_na = __syncthreads_or(na);
    if (tid == 0) {
        float m = s_rmax[0]; int midx = s_rmaxi[0];
        for (int w = 1; w < 32; w++) {
            if (s_rmax[w] > m || (s_rmax[w] == m && s_rmaxi[w] < midx)) {
                m = s_rmax[w]; midx = s_rmaxi[w];
            }
        }
        s_maxidx = midx;
        g_midx = midx;
    }
    __syncthreads();

    if (any_na) {
        if (tid == 0) {
            int midx = s_maxidx;
            bool maxRe = false;
            for (int i = NB - 1; i >= 0; --i) {
                if (s_na[i]) {
                    float na2 = s_aem[midx] * 0.5f;
                    s_code[i] = maxRe ? 2 : 1;
                    s_aem[i] = na2;
                    s_aem[midx] = na2;
                    if (i == midx) maxRe = true;
                }
            }
        }
        __syncthreads();
    }

    g_code[tid] = s_code[tid];
    out[1 + NB * DZ + tid] = s_aem[tid];

    if (tid == 0) {
        double recon = 0.5 * (g_recon / (double)NROWS)
                     + 32.0 * 1.8378770664093453;   // 0.5*d_x*log(2*pi)
        double commit = g_commit / ((double)NROWS * (double)DZ);
        out[0] = (float)(recon + 0.25 * commit);
    }
}

// ---------------------------------------------------------------------------
// final2: new_vectors (parallel, 32 blocks x 1024)
// ---------------------------------------------------------------------------
__global__ void k_final2(const float* __restrict__ vectors,
                         const float* __restrict__ noise,
                         float* __restrict__ out)
{
    int n = blockIdx.x * 1024 + threadIdx.x;  // 0..32767
    int b = n >> 5, d = n & 31;
    int midx = g_midx;
    float sz = g_sum[n];
    unsigned char code = g_code[b];
    float v2;
    if (code == 0) {
        v2 = vectors[n];
    } else {
        v2 = vectors[midx * DZ + d] + noise[n];
        if (code == 2) v2 += noise[midx * DZ + d];
    }
    float cntb = g_cnt[b];
    float mean = (cntb > 0.f) ? (sz / cntb) : v2;
    out[1 + n] = 0.99f * v2 + 0.01f * mean;
}

// ---------------------------------------------------------------------------
extern "C" void kernel_launch(void* const* d_in, const int* in_sizes, int n_in,
                              void* d_out, int out_size) {
    const float* x           = (const float*)d_in[0];
    const float* W_enc       = (const float*)d_in[1];
    const float* b_enc       = (const float*)d_in[2];
    const float* vectors     = (const float*)d_in[3];
    const float* W_dec       = (const float*)d_in[4];
    const float* b_dec       = (const float*)d_in[5];
    const float* assignments = (const float*)d_in[6];
    const float* noise       = (const float*)d_in[7];
    float* out = (float*)d_out;

    cudaFuncSetAttribute(k_main, cudaFuncAttributeMaxDynamicSharedMemorySize,
                         SMEM_MAIN);

    k_init<<<128, 256>>>(vectors, W_enc, W_dec);
    k_main<<<GRID_MAIN, 256, SMEM_MAIN>>>(x, b_enc, vectors, b_dec);
    k_final1<<<1, 1024>>>(assignments, out);
    k_final2<<<32, 1024>>>(vectors, noise, out);
}